// round 2
// baseline (speedup 1.0000x reference)
#include <cuda_runtime.h>
#include <cuda_bf16.h>

// Problem constants
#define S_LEN   4096
#define K_CH    4
#define NCHAR   (S_LEN * K_CH)      // 16384 char steps
#define A_SZ    25
#define EC      64
#define HR      256
#define DL      128
#define EW      128
#define HW      512
#define ZR      (4 * HR)            // 1024
#define ZW      (4 * HW)            // 2048
#define GBLK    32                  // persistent CTAs for both recurrences

// ---------------- scratch (static __device__ — no allocations) ----------------
__device__ float d_zalpha[A_SZ * ZR];          // per-letter char input projection (+b_r)
__device__ float d_hhist[NCHAR * HR];          // full char-LSTM h history (also the h-exchange medium)
__device__ float d_xw[S_LEN * ZW];             // word-LSTM input projections (+b_w)

__device__ unsigned g_cnt1 = 0u;  __device__ unsigned g_ep1 = 0u;   // char barrier
__device__ unsigned g_cnt3 = 0u;  __device__ unsigned g_ep3 = 0u;   // word barrier

// ---------------- helpers ----------------
__device__ __forceinline__ float sigm(float x) { return 1.0f / (1.0f + __expf(-x)); }

// Monotonic-epoch grid barrier (no reset needed across graph replays).
__device__ __forceinline__ void gridbar(unsigned* cnt, volatile unsigned* ep, unsigned G) {
    __threadfence();
    __syncthreads();
    if (threadIdx.x == 0) {
        unsigned t   = atomicAdd(cnt, 1u);
        unsigned tgt = t / G + 1u;
        if (t % G == G - 1u) {
            __threadfence();
            *ep = tgt;
        } else {
            while (*ep < tgt) { }
        }
        __threadfence();
    }
    __syncthreads();
}

// ---------------- K0: Z_alpha = E_char @ W_ih_r^T + b_r  [25 x 1024] ----------------
__global__ void k_zalpha(const float* __restrict__ E_char,
                         const float* __restrict__ W_ih_r,
                         const float* __restrict__ b_r) {
    __shared__ float es[EC];
    int a = blockIdx.x;
    if (threadIdx.x < EC) es[threadIdx.x] = E_char[a * EC + threadIdx.x];
    __syncthreads();
    for (int r = threadIdx.x; r < ZR; r += blockDim.x) {
        float acc = b_r[r];
        const float* wr = W_ih_r + r * EC;
        #pragma unroll 16
        for (int e = 0; e < EC; e++) acc += wr[e] * es[e];
        d_zalpha[a * ZR + r] = acc;
    }
}

// ---------------- K1: char-LSTM recurrence (32 CTAs x 256 thr, W_hh_r in regs) -------
// CTA b owns hidden units j in [8b, 8b+8); warp u handles unit j=8b+u; within the warp
// lanes [8q,8q+8) compute gate q's dot product over strided column chunks.
__global__ void __launch_bounds__(256, 1)
k_char(const float* __restrict__ W_hh, const int* __restrict__ cid) {
    __shared__ float hs[HR];
    const int tid  = threadIdx.x;
    const int u    = tid >> 5;
    const int lane = tid & 31;
    const int q    = lane >> 3;
    const int s8   = lane & 7;
    const int j    = blockIdx.x * 8 + u;
    const int row  = q * HR + j;

    // weights in registers: col(kk,m) = s8*4 + kk*32 + m  (bank-conflict-free h reads)
    float w[32];
    #pragma unroll
    for (int kk = 0; kk < 8; kk++) {
        float4 v = *(const float4*)(W_hh + row * HR + s8 * 4 + kk * 32);
        w[kk*4+0] = v.x; w[kk*4+1] = v.y; w[kk*4+2] = v.z; w[kk*4+3] = v.w;
    }

    float cst = 0.0f;
    for (int t = 0; t < NCHAR; t++) {
        float acc = 0.0f;
        if (t > 0) {
            if (tid < HR / 4) {
                float4 v = __ldcg((const float4*)(d_hhist + (size_t)(t - 1) * HR) + tid);
                ((float4*)hs)[tid] = v;
            }
            __syncthreads();
            #pragma unroll
            for (int kk = 0; kk < 8; kk++) {
                float4 hv = *(const float4*)(hs + s8 * 4 + kk * 32);
                acc += w[kk*4+0]*hv.x + w[kk*4+1]*hv.y + w[kk*4+2]*hv.z + w[kk*4+3]*hv.w;
            }
        }
        float xv = 0.0f;
        if (s8 == 0) {
            int ct = __ldg(cid + t);
            xv = __ldg(d_zalpha + ct * ZR + row);
        }
        acc += __shfl_xor_sync(0xffffffffu, acc, 4);
        acc += __shfl_xor_sync(0xffffffffu, acc, 2);
        acc += __shfl_xor_sync(0xffffffffu, acc, 1);
        acc += xv;                                   // valid on lanes 0,8,16,24
        float zf = __shfl_sync(0xffffffffu, acc, 8);
        float zg = __shfl_sync(0xffffffffu, acc, 16);
        float zo = __shfl_sync(0xffffffffu, acc, 24);
        if (lane == 0) {
            float zi = acc;
            cst = sigm(zf) * cst + sigm(zi) * tanhf(zg);
            float h = sigm(zo) * tanhf(cst);
            d_hhist[(size_t)t * HR + j] = h;
        }
        gridbar(&g_cnt1, &g_ep1, GBLK);
    }
}

// ---------------- K2: latent + word input projections ----------------
// block handles 16 sentences: latent = tanh(h_word @ W_lat^T + b_lat);
// X_w = [we, latent] @ W_ih_w^T + b_w
__global__ void __launch_bounds__(256)
k_wordin(const float* __restrict__ W_lat, const float* __restrict__ b_lat,
         const float* __restrict__ E_word, const float* __restrict__ W_ih_w,
         const float* __restrict__ b_w,   const int* __restrict__ word_ids) {
    __shared__ float hw[16 * HR];          // 16 KB
    __shared__ float us[16 * (EW + DL)];   // 16 KB : [si][0:128)=we, [128:256)=latent
    const int tid = threadIdx.x;
    const int s0  = blockIdx.x * 16;

    #pragma unroll
    for (int i = 0; i < 16; i++)
        hw[i * HR + tid] = d_hhist[(size_t)(4 * (s0 + i) + 3) * HR + tid];
    for (int idx = tid; idx < 16 * EW; idx += 256) {
        int si = idx >> 7, e = idx & 127;
        us[si * 256 + e] = __ldg(E_word + (size_t)__ldg(word_ids + s0 + si) * EW + e);
    }
    __syncthreads();

    for (int idx = tid; idx < 16 * DL; idx += 256) {
        int si = idx >> 7, d = idx & 127;
        float acc = b_lat[d];
        const float* wr = W_lat + d * HR;
        #pragma unroll 8
        for (int l = 0; l < HR; l++) acc += __ldg(wr + l) * hw[si * HR + l];
        us[si * 256 + 128 + d] = tanhf(acc);
    }
    __syncthreads();

    for (int rr = 0; rr < 8; rr++) {
        int r = tid + rr * 256;
        const float* wr = W_ih_w + (size_t)r * 256;
        float bb = b_w[r];
        float acc[16];
        #pragma unroll
        for (int si = 0; si < 16; si++) acc[si] = bb;
        for (int c = 0; c < 256; c++) {
            float wv = __ldg(wr + c);
            #pragma unroll
            for (int si = 0; si < 16; si++) acc[si] += wv * us[si * 256 + c];
        }
        #pragma unroll
        for (int si = 0; si < 16; si++) d_xw[(size_t)(s0 + si) * ZW + r] = acc[si];
    }
}

// ---------------- K3: word-LSTM recurrence (32 CTAs x 512 thr, W_hh_w in regs) -------
// d_out doubles as the h history / exchange medium.
__global__ void __launch_bounds__(512, 1)
k_word(const float* __restrict__ W_hh, float* __restrict__ out) {
    __shared__ float hs[HW];
    const int tid  = threadIdx.x;
    const int u    = tid >> 5;
    const int lane = tid & 31;
    const int q    = lane >> 3;
    const int s8   = lane & 7;
    const int j    = blockIdx.x * 16 + u;
    const int row  = q * HW + j;

    float w[64];
    #pragma unroll
    for (int kk = 0; kk < 16; kk++) {
        float4 v = *(const float4*)(W_hh + (size_t)row * HW + s8 * 4 + kk * 32);
        w[kk*4+0] = v.x; w[kk*4+1] = v.y; w[kk*4+2] = v.z; w[kk*4+3] = v.w;
    }

    float cst = 0.0f;
    for (int t = 0; t < S_LEN; t++) {
        float acc = 0.0f;
        if (t > 0) {
            if (tid < HW / 4) {
                float4 v = __ldcg((const float4*)(out + (size_t)(t - 1) * HW) + tid);
                ((float4*)hs)[tid] = v;
            }
            __syncthreads();
            #pragma unroll
            for (int kk = 0; kk < 16; kk++) {
                float4 hv = *(const float4*)(hs + s8 * 4 + kk * 32);
                acc += w[kk*4+0]*hv.x + w[kk*4+1]*hv.y + w[kk*4+2]*hv.z + w[kk*4+3]*hv.w;
            }
        }
        float xv = 0.0f;
        if (s8 == 0) xv = __ldg(d_xw + (size_t)t * ZW + row);
        acc += __shfl_xor_sync(0xffffffffu, acc, 4);
        acc += __shfl_xor_sync(0xffffffffu, acc, 2);
        acc += __shfl_xor_sync(0xffffffffu, acc, 1);
        acc += xv;
        float zf = __shfl_sync(0xffffffffu, acc, 8);
        float zg = __shfl_sync(0xffffffffu, acc, 16);
        float zo = __shfl_sync(0xffffffffu, acc, 24);
        if (lane == 0) {
            float zi = acc;
            cst = sigm(zf) * cst + sigm(zi) * tanhf(zg);
            float h = sigm(zo) * tanhf(cst);
            out[(size_t)t * HW + j] = h;
        }
        gridbar(&g_cnt3, &g_ep3, GBLK);
    }
}

// ---------------- launch ----------------
extern "C" void kernel_launch(void* const* d_in, const int* in_sizes, int n_in,
                              void* d_out, int out_size) {
    const float* E_char  = (const float*)d_in[0];
    const float* W_ih_r  = (const float*)d_in[1];
    const float* W_hh_r  = (const float*)d_in[2];
    const float* b_r     = (const float*)d_in[3];
    const float* W_lat   = (const float*)d_in[4];
    const float* b_lat   = (const float*)d_in[5];
    const float* E_word  = (const float*)d_in[6];
    const float* W_ih_w  = (const float*)d_in[7];
    const float* W_hh_w  = (const float*)d_in[8];
    const float* b_w     = (const float*)d_in[9];
    const int*   word_ids = (const int*)d_in[10];
    const int*   char_ids = (const int*)d_in[11];
    float* out = (float*)d_out;

    k_zalpha<<<A_SZ, 256>>>(E_char, W_ih_r, b_r);
    k_char<<<GBLK, 256>>>(W_hh_r, char_ids);
    k_wordin<<<S_LEN / 16, 256>>>(W_lat, b_lat, E_word, W_ih_w, b_w, word_ids);
    k_word<<<GBLK, 512>>>(W_hh_w, out);
}

// round 6
// speedup vs baseline: 1.6839x; 1.6839x over previous
#include <cuda_runtime.h>
#include <cuda_bf16.h>

// Problem constants
#define S_LEN   4096
#define K_CH    4
#define NCHAR   (S_LEN * K_CH)      // 16384 char steps
#define A_SZ    25
#define EC      64
#define HR      256
#define DL      128
#define EW      128
#define HW      512
#define ZR      (4 * HR)            // 1024
#define ZW      (4 * HW)            // 2048
#define GBLK    32                  // persistent CTAs for both recurrences

// ---------------- scratch (static __device__ — no allocations) ----------------
__device__ float d_zalpha[A_SZ * ZR];          // per-letter char input projection (+b_r)
__device__ float d_hhist[NCHAR * HR];          // char-LSTM h history
__device__ float d_xw[S_LEN * ZW];             // word-LSTM input projections (+b_w)
__device__ int   d_flg_c[GBLK * 32];           // per-CTA monotonic step flags (stride 32 = own 128B line)
__device__ int   d_flg_w[GBLK * 32];

// ---------------- helpers ----------------
__device__ __forceinline__ float sigm(float x) { return 1.0f / (1.0f + __expf(-x)); }

// Warp 0, lane c spins on producer CTA c's flag until it reaches `t`.
// Guard (2^16 ~ 10ms) covers transient excursions without risking silent corruption
// in normal operation; systemic failure degrades to slow-but-finite, diagnosable.
__device__ __forceinline__ void wait_flag_lane(volatile int* f, int t) {
    int guard = 0;
    while (*f < t) { if (++guard > (1 << 16)) break; }
}

// ---------------- K-1: zero the flag arrays (kernels-only graph) ----------------
__global__ void k_fill() {
    int i = threadIdx.x;
    if (i < GBLK * 32) { d_flg_c[i] = 0; d_flg_w[i] = 0; }
}

// ---------------- K0: Z_alpha = E_char @ W_ih_r^T + b_r  [25 x 1024] ----------------
__global__ void k_zalpha(const float* __restrict__ E_char,
                         const float* __restrict__ W_ih_r,
                         const float* __restrict__ b_r) {
    __shared__ float es[EC];
    int a = blockIdx.x;
    if (threadIdx.x < EC) es[threadIdx.x] = E_char[a * EC + threadIdx.x];
    __syncthreads();
    for (int r = threadIdx.x; r < ZR; r += blockDim.x) {
        float acc = b_r[r];
        const float* wr = W_ih_r + r * EC;
        #pragma unroll 16
        for (int e = 0; e < EC; e++) acc += wr[e] * es[e];
        d_zalpha[a * ZR + r] = acc;
    }
}

// ---------------- K1: char-LSTM recurrence (32 CTAs x 256 thr, W_hh_r in regs) -------
// CTA b owns units [8b,8b+8); warp u -> unit j=8b+u; lanes [8q,8q+8) compute gate q.
// Publication: h stores (st.cg) -> __threadfence -> __syncthreads -> flag[cta]=t+1.
__global__ void __launch_bounds__(256, 1)
k_char(const float* __restrict__ W_hh, const int* __restrict__ cid) {
    __shared__ float hs[HR];
    const int tid  = threadIdx.x;
    const int u    = tid >> 5;
    const int lane = tid & 31;
    const int q    = lane >> 3;
    const int s8   = lane & 7;
    const int j    = blockIdx.x * 8 + u;
    const int row  = q * HR + j;

    float w[32];
    #pragma unroll
    for (int kk = 0; kk < 8; kk++) {
        float4 v = *(const float4*)(W_hh + row * HR + s8 * 4 + kk * 32);
        w[kk*4+0] = v.x; w[kk*4+1] = v.y; w[kk*4+2] = v.z; w[kk*4+3] = v.w;
    }

    float cst = 0.0f;
    for (int t = 0; t < NCHAR; t++) {
        // independent input-projection lookup first (hides under poll + h load)
        float xv = 0.0f;
        if (s8 == 0) {
            int ct = __ldg(cid + t);
            xv = __ldg(d_zalpha + ct * ZR + row);
        }
        float acc = 0.0f;
        if (t > 0) {
            if (u == 0) wait_flag_lane((volatile int*)&d_flg_c[lane * 32], t);  // 32 parallel spins
            __syncthreads();
            if (tid < HR / 4) {
                float4 v = __ldcg((const float4*)(d_hhist + (size_t)(t - 1) * HR) + tid);
                ((float4*)hs)[tid] = v;
            }
            __syncthreads();
            #pragma unroll
            for (int kk = 0; kk < 8; kk++) {
                float4 hv = *(const float4*)(hs + s8 * 4 + kk * 32);
                acc += w[kk*4+0]*hv.x + w[kk*4+1]*hv.y + w[kk*4+2]*hv.z + w[kk*4+3]*hv.w;
            }
        }
        acc += __shfl_xor_sync(0xffffffffu, acc, 4);
        acc += __shfl_xor_sync(0xffffffffu, acc, 2);
        acc += __shfl_xor_sync(0xffffffffu, acc, 1);
        acc += xv;                                   // valid on lanes 0,8,16,24
        float zf = __shfl_sync(0xffffffffu, acc, 8);
        float zg = __shfl_sync(0xffffffffu, acc, 16);
        float zo = __shfl_sync(0xffffffffu, acc, 24);
        if (lane == 0) {
            float zi = acc;
            cst = sigm(zf) * cst + sigm(zi) * tanhf(zg);
            float h = sigm(zo) * tanhf(cst);
            __stcg(d_hhist + (size_t)t * HR + j, h);
        }
        __threadfence();                              // order h stores before the flag
        __syncthreads();                              // also protects hs for next step
        if (tid == 0) *(volatile int*)&d_flg_c[blockIdx.x * 32] = t + 1;
    }
}

// ---------------- K2: latent + word input projections ----------------
__global__ void __launch_bounds__(256)
k_wordin(const float* __restrict__ W_lat, const float* __restrict__ b_lat,
         const float* __restrict__ E_word, const float* __restrict__ W_ih_w,
         const float* __restrict__ b_w,   const int* __restrict__ word_ids) {
    __shared__ float hw[16 * HR];          // 16 KB
    __shared__ float us[16 * (EW + DL)];   // 16 KB : [si][0:128)=we, [128:256)=latent
    const int tid = threadIdx.x;
    const int s0  = blockIdx.x * 16;

    #pragma unroll
    for (int i = 0; i < 16; i++)
        hw[i * HR + tid] = d_hhist[(size_t)(4 * (s0 + i) + 3) * HR + tid];
    for (int idx = tid; idx < 16 * EW; idx += 256) {
        int si = idx >> 7, e = idx & 127;
        us[si * 256 + e] = __ldg(E_word + (size_t)__ldg(word_ids + s0 + si) * EW + e);
    }
    __syncthreads();

    for (int idx = tid; idx < 16 * DL; idx += 256) {
        int si = idx >> 7, d = idx & 127;
        float acc = b_lat[d];
        const float* wr = W_lat + d * HR;
        #pragma unroll 8
        for (int l = 0; l < HR; l++) acc += __ldg(wr + l) * hw[si * HR + l];
        us[si * 256 + 128 + d] = tanhf(acc);
    }
    __syncthreads();

    for (int rr = 0; rr < 8; rr++) {
        int r = tid + rr * 256;
        const float* wr = W_ih_w + (size_t)r * 256;
        float bb = b_w[r];
        float acc[16];
        #pragma unroll
        for (int si = 0; si < 16; si++) acc[si] = bb;
        for (int c = 0; c < 256; c++) {
            float wv = __ldg(wr + c);
            #pragma unroll
            for (int si = 0; si < 16; si++) acc[si] += wv * us[si * 256 + c];
        }
        #pragma unroll
        for (int si = 0; si < 16; si++) d_xw[(size_t)(s0 + si) * ZW + r] = acc[si];
    }
}

// ---------------- K3: word-LSTM recurrence (32 CTAs x 256 thr, 2 units/warp) ---------
// NOTE: d_xw is referenced from DEVICE code here (the R5 bug was passing the __device__
// symbol as a host-side kernel argument -> host shadow address -> illegal access).
__global__ void __launch_bounds__(256, 1)
k_word(const float* __restrict__ W_hh, float* __restrict__ out) {
    __shared__ float hs[HW];
    const int tid  = threadIdx.x;
    const int u    = tid >> 5;
    const int lane = tid & 31;
    const int q    = lane >> 3;
    const int s8   = lane & 7;
    const int j0   = blockIdx.x * 16 + u * 2;
    const int j1   = j0 + 1;
    const int row0 = q * HW + j0;
    const int row1 = q * HW + j1;

    float w0[64], w1[64];
    #pragma unroll
    for (int kk = 0; kk < 16; kk++) {
        float4 a = *(const float4*)(W_hh + (size_t)row0 * HW + s8 * 4 + kk * 32);
        w0[kk*4+0] = a.x; w0[kk*4+1] = a.y; w0[kk*4+2] = a.z; w0[kk*4+3] = a.w;
        float4 b = *(const float4*)(W_hh + (size_t)row1 * HW + s8 * 4 + kk * 32);
        w1[kk*4+0] = b.x; w1[kk*4+1] = b.y; w1[kk*4+2] = b.z; w1[kk*4+3] = b.w;
    }

    float cst0 = 0.0f, cst1 = 0.0f;
    for (int t = 0; t < S_LEN; t++) {
        float xv0 = 0.0f, xv1 = 0.0f;
        if (s8 == 0) {                                  // prefetch, independent of h
            xv0 = __ldg(d_xw + (size_t)t * ZW + row0);
            xv1 = __ldg(d_xw + (size_t)t * ZW + row1);
        }
        float acc0 = 0.0f, acc1 = 0.0f;
        if (t > 0) {
            if (u == 0) wait_flag_lane((volatile int*)&d_flg_w[lane * 32], t);
            __syncthreads();
            if (tid < HW / 4) {
                float4 v = __ldcg((const float4*)(out + (size_t)(t - 1) * HW) + tid);
                ((float4*)hs)[tid] = v;
            }
            __syncthreads();
            #pragma unroll
            for (int kk = 0; kk < 16; kk++) {
                float4 hv = *(const float4*)(hs + s8 * 4 + kk * 32);
                acc0 += w0[kk*4+0]*hv.x + w0[kk*4+1]*hv.y + w0[kk*4+2]*hv.z + w0[kk*4+3]*hv.w;
                acc1 += w1[kk*4+0]*hv.x + w1[kk*4+1]*hv.y + w1[kk*4+2]*hv.z + w1[kk*4+3]*hv.w;
            }
        }
        #pragma unroll
        for (int d = 4; d >= 1; d >>= 1) {
            acc0 += __shfl_xor_sync(0xffffffffu, acc0, d);
            acc1 += __shfl_xor_sync(0xffffffffu, acc1, d);
        }
        acc0 += xv0;  acc1 += xv1;                      // valid on lanes 0,8,16,24
        float zf0 = __shfl_sync(0xffffffffu, acc0, 8);
        float zg0 = __shfl_sync(0xffffffffu, acc0, 16);
        float zo0 = __shfl_sync(0xffffffffu, acc0, 24);
        float zf1 = __shfl_sync(0xffffffffu, acc1, 8);
        float zg1 = __shfl_sync(0xffffffffu, acc1, 16);
        float zo1 = __shfl_sync(0xffffffffu, acc1, 24);
        if (lane == 0) {
            cst0 = sigm(zf0) * cst0 + sigm(acc0) * tanhf(zg0);
            float h0 = sigm(zo0) * tanhf(cst0);
            cst1 = sigm(zf1) * cst1 + sigm(acc1) * tanhf(zg1);
            float h1 = sigm(zo1) * tanhf(cst1);
            __stcg(out + (size_t)t * HW + j0, h0);
            __stcg(out + (size_t)t * HW + j1, h1);
        }
        __threadfence();
        __syncthreads();
        if (tid == 0) *(volatile int*)&d_flg_w[blockIdx.x * 32] = t + 1;
    }
}

// ---------------- launch ----------------
extern "C" void kernel_launch(void* const* d_in, const int* in_sizes, int n_in,
                              void* d_out, int out_size) {
    const float* E_char  = (const float*)d_in[0];
    const float* W_ih_r  = (const float*)d_in[1];
    const float* W_hh_r  = (const float*)d_in[2];
    const float* b_r     = (const float*)d_in[3];
    const float* W_lat   = (const float*)d_in[4];
    const float* b_lat   = (const float*)d_in[5];
    const float* E_word  = (const float*)d_in[6];
    const float* W_ih_w  = (const float*)d_in[7];
    const float* W_hh_w  = (const float*)d_in[8];
    const float* b_w     = (const float*)d_in[9];
    const int*   word_ids = (const int*)d_in[10];
    const int*   char_ids = (const int*)d_in[11];
    float* out = (float*)d_out;

    k_fill<<<1, 1024>>>();                     // zero monotonic flags each run
    k_zalpha<<<A_SZ, 256>>>(E_char, W_ih_r, b_r);
    k_char<<<GBLK, 256>>>(W_hh_r, char_ids);
    k_wordin<<<S_LEN / 16, 256>>>(W_lat, b_lat, E_word, W_ih_w, b_w, word_ids);
    k_word<<<GBLK, 256>>>(W_hh_w, out);
}

// round 8
// speedup vs baseline: 1.9593x; 1.1635x over previous
#include <cuda_runtime.h>
#include <cuda_bf16.h>
#include <cstdint>

// Problem constants
#define S_LEN   4096
#define K_CH    4
#define NCHAR   (S_LEN * K_CH)      // 16384 char steps
#define A_SZ    25
#define EC      64
#define HR      256
#define DL      128
#define EW      128
#define HW      512
#define ZR      (4 * HR)            // 1024
#define ZW      (4 * HW)            // 2048
#define GBLK    32                  // CTAs for the word recurrence
#define CL      8                   // cluster size for the char recurrence

// ---------------- scratch (static __device__ — no allocations) ----------------
__device__ float d_zalpha[A_SZ * ZR];          // per-letter char input projection (+b_r)
__device__ float d_hword[S_LEN * HR];          // char-LSTM h at word boundaries only
__device__ float d_xw[S_LEN * ZW];             // word-LSTM input projections (+b_w)
__device__ int   d_flg_w[GBLK * 32];           // word per-CTA monotonic step flags

#define SENT 0xFFFFFFFFu                        // negative NaN bit pattern; h in (-1,1) never encodes it

// ---------------- helpers ----------------
__device__ __forceinline__ float sigm(float x) { return 1.0f / (1.0f + __expf(-x)); }

__device__ __forceinline__ uint32_t smem_u32(const void* p) {
    uint32_t a;
    asm("{ .reg .u64 t; cvta.to.shared.u64 t, %1; cvt.u32.u64 %0, t; }" : "=r"(a) : "l"(p));
    return a;
}
__device__ __forceinline__ uint32_t mapa_rank(uint32_t laddr, uint32_t rank) {
    uint32_t r;
    asm("mapa.shared::cluster.u32 %0, %1, %2;" : "=r"(r) : "r"(laddr), "r"(rank));
    return r;
}
__device__ __forceinline__ void st_cluster_v4(uint32_t raddr, float a, float b, float c, float d) {
    asm volatile("st.shared::cluster.v4.f32 [%0], {%1,%2,%3,%4};"
                 :: "r"(raddr), "f"(a), "f"(b), "f"(c), "f"(d) : "memory");
}
__device__ __forceinline__ uint32_t my_cluster_rank() {
    uint32_t r; asm("mov.u32 %0, %%cluster_ctarank;" : "=r"(r)); return r;
}
// Word-LSTM flag spin (R6-proven primitive).
__device__ __forceinline__ void wait_flag_lane(volatile int* f, int t) {
    int guard = 0;
    while (*f < t) { if (++guard > (1 << 16)) break; }
}

// ---------------- K-1: zero the word flag array ----------------
__global__ void k_fill() {
    int i = threadIdx.x;
    if (i < GBLK * 32) d_flg_w[i] = 0;
}

// ---------------- K0: Z_alpha = E_char @ W_ih_r^T + b_r  [25 x 1024] ----------------
__global__ void k_zalpha(const float* __restrict__ E_char,
                         const float* __restrict__ W_ih_r,
                         const float* __restrict__ b_r) {
    __shared__ float es[EC];
    int a = blockIdx.x;
    if (threadIdx.x < EC) es[threadIdx.x] = E_char[a * EC + threadIdx.x];
    __syncthreads();
    for (int r = threadIdx.x; r < ZR; r += blockDim.x) {
        float acc = b_r[r];
        const float* wr = W_ih_r + r * EC;
        #pragma unroll 16
        for (int e = 0; e < EC; e++) acc += wr[e] * es[e];
        d_zalpha[a * ZR + r] = acc;
    }
}

// ---------------- K1: char-LSTM — 8-CTA cluster, DSMEM push + local sentinel poll ----
// CTA rank owns units [32r, 32r+32); warp u owns 4 units jb..jb+3 (jb = 32r + 4u).
// Lanes [8q,8q+8) compute gate q. h exchange: producers push h into every CTA's
// hbuf[slot] via st.shared::cluster; consumers poll their OWN SMEM for sentinel-clear.
__global__ void __launch_bounds__(256, 1) __cluster_dims__(CL, 1, 1)
k_char(const float* __restrict__ W_hh, const int* __restrict__ cid) {
    __shared__ float hbuf[2][HR];                 // double-buffered h exchange slots
    const int tid  = threadIdx.x;
    const int u    = tid >> 5;
    const int lane = tid & 31;
    const int q    = lane >> 3;
    const int s8   = lane & 7;
    const uint32_t rank = my_cluster_rank();
    const int jb   = (int)rank * 32 + u * 4;

    // register-resident weights: 4 units x 32 floats
    float w[4][32];
    #pragma unroll
    for (int m = 0; m < 4; m++) {
        const float* base = W_hh + (size_t)(q * HR + jb + m) * HR;
        #pragma unroll
        for (int kk = 0; kk < 8; kk++) {
            float4 v = *(const float4*)(base + s8 * 4 + kk * 32);
            w[m][kk*4+0] = v.x; w[m][kk*4+1] = v.y; w[m][kk*4+2] = v.z; w[m][kk*4+3] = v.w;
        }
    }

    // sentinel both slots; cluster-sync so no CTA publishes before all are initialized
    ((uint32_t*)hbuf)[tid]       = SENT;
    ((uint32_t*)hbuf)[tid + HR]  = SENT;
    __syncthreads();
    asm volatile("barrier.cluster.arrive.aligned;" ::: "memory");
    asm volatile("barrier.cluster.wait.aligned;"   ::: "memory");

    const uint32_t hb_base = smem_u32(hbuf);
    float cst[4] = {0.f, 0.f, 0.f, 0.f};

    for (int t = 0; t < NCHAR; t++) {
        float xv[4] = {0.f, 0.f, 0.f, 0.f};
        if (s8 == 0) {
            int ct = __ldg(cid + t);
            const float* za = d_zalpha + ct * ZR + q * HR + jb;
            #pragma unroll
            for (int m = 0; m < 4; m++) xv[m] = __ldg(za + m);
        }
        float acc[4] = {0.f, 0.f, 0.f, 0.f};
        if (t > 0) {
            const int ps = (t - 1) & 1;
            {   // each thread polls one word of the previous-step slot (local SMEM)
                volatile uint32_t* p = (volatile uint32_t*)&hbuf[ps][0] + tid;
                int g = 0;
                while (*p == SENT) { if (++g > (1 << 16)) break; }
            }
            __syncthreads();
            #pragma unroll
            for (int kk = 0; kk < 8; kk++) {
                float4 hv = *(const float4*)(&hbuf[ps][s8 * 4 + kk * 32]);
                #pragma unroll
                for (int m = 0; m < 4; m++)
                    acc[m] += w[m][kk*4+0]*hv.x + w[m][kk*4+1]*hv.y
                            + w[m][kk*4+2]*hv.z + w[m][kk*4+3]*hv.w;
            }
            __syncthreads();                               // all reads of slot ps done
            ((uint32_t*)&hbuf[ps][0])[tid] = SENT;         // re-sentinel for epoch t+1
            __syncthreads();                               // re-sentinel before publish
        }
        // gate reduce + cell update per unit (warp-redundant; lane0's state is truth)
        float h[4];
        #pragma unroll
        for (int m = 0; m < 4; m++) {
            float a = acc[m] + xv[m];                      // xv on s8==0 only: summed once
            a += __shfl_xor_sync(0xffffffffu, a, 4);
            a += __shfl_xor_sync(0xffffffffu, a, 2);
            a += __shfl_xor_sync(0xffffffffu, a, 1);
            float zi = __shfl_sync(0xffffffffu, a, 0);
            float zf = __shfl_sync(0xffffffffu, a, 8);
            float zg = __shfl_sync(0xffffffffu, a, 16);
            float zo = __shfl_sync(0xffffffffu, a, 24);
            float c  = sigm(zf) * cst[m] + sigm(zi) * tanhf(zg);
            cst[m] = c;
            h[m] = sigm(zo) * tanhf(c);
        }
        // push this warp's 4 h values into all 8 CTAs' hbuf[t&1] (incl. self)
        if (lane < CL) {
            uint32_t laddr = hb_base + (uint32_t)(((t & 1) * HR + jb) * 4);
            uint32_t raddr = mapa_rank(laddr, (uint32_t)lane);
            st_cluster_v4(raddr, h[0], h[1], h[2], h[3]);
        }
        // word-boundary h out to global for the word-LSTM input stage
        if ((t & 3) == 3 && lane == 0)
            *(float4*)&d_hword[(size_t)(t >> 2) * HR + jb] = make_float4(h[0], h[1], h[2], h[3]);
    }
    // no CTA may exit while peers might still push into its SMEM
    asm volatile("barrier.cluster.arrive.aligned;" ::: "memory");
    asm volatile("barrier.cluster.wait.aligned;"   ::: "memory");
}

// ---------------- K2: latent + word input projections ----------------
__global__ void __launch_bounds__(256)
k_wordin(const float* __restrict__ W_lat, const float* __restrict__ b_lat,
         const float* __restrict__ E_word, const float* __restrict__ W_ih_w,
         const float* __restrict__ b_w,   const int* __restrict__ word_ids) {
    __shared__ float hw[16 * HR];          // 16 KB
    __shared__ float us[16 * (EW + DL)];   // 16 KB : [si][0:128)=we, [128:256)=latent
    const int tid = threadIdx.x;
    const int s0  = blockIdx.x * 16;

    #pragma unroll
    for (int i = 0; i < 16; i++)
        hw[i * HR + tid] = d_hword[(size_t)(s0 + i) * HR + tid];
    for (int idx = tid; idx < 16 * EW; idx += 256) {
        int si = idx >> 7, e = idx & 127;
        us[si * 256 + e] = __ldg(E_word + (size_t)__ldg(word_ids + s0 + si) * EW + e);
    }
    __syncthreads();

    for (int idx = tid; idx < 16 * DL; idx += 256) {
        int si = idx >> 7, d = idx & 127;
        float acc = b_lat[d];
        const float* wr = W_lat + d * HR;
        #pragma unroll 8
        for (int l = 0; l < HR; l++) acc += __ldg(wr + l) * hw[si * HR + l];
        us[si * 256 + 128 + d] = tanhf(acc);
    }
    __syncthreads();

    for (int rr = 0; rr < 8; rr++) {
        int r = tid + rr * 256;
        const float* wr = W_ih_w + (size_t)r * 256;
        float bb = b_w[r];
        float acc[16];
        #pragma unroll
        for (int si = 0; si < 16; si++) acc[si] = bb;
        for (int c = 0; c < 256; c++) {
            float wv = __ldg(wr + c);
            #pragma unroll
            for (int si = 0; si < 16; si++) acc[si] += wv * us[si * 256 + c];
        }
        #pragma unroll
        for (int si = 0; si < 16; si++) d_xw[(size_t)(s0 + si) * ZW + r] = acc[si];
    }
}

// ---------------- K3: word-LSTM recurrence (32 CTAs x 256 thr, 2 units/warp) ---------
// L2 flag scheme (R6-proven); fence by tid0 only, after __syncthreads.
__global__ void __launch_bounds__(256, 1)
k_word(const float* __restrict__ W_hh, float* __restrict__ out) {
    __shared__ float hs[HW];
    const int tid  = threadIdx.x;
    const int u    = tid >> 5;
    const int lane = tid & 31;
    const int q    = lane >> 3;
    const int s8   = lane & 7;
    const int j0   = blockIdx.x * 16 + u * 2;
    const int j1   = j0 + 1;
    const int row0 = q * HW + j0;
    const int row1 = q * HW + j1;

    float w0[64], w1[64];
    #pragma unroll
    for (int kk = 0; kk < 16; kk++) {
        float4 a = *(const float4*)(W_hh + (size_t)row0 * HW + s8 * 4 + kk * 32);
        w0[kk*4+0] = a.x; w0[kk*4+1] = a.y; w0[kk*4+2] = a.z; w0[kk*4+3] = a.w;
        float4 b = *(const float4*)(W_hh + (size_t)row1 * HW + s8 * 4 + kk * 32);
        w1[kk*4+0] = b.x; w1[kk*4+1] = b.y; w1[kk*4+2] = b.z; w1[kk*4+3] = b.w;
    }

    float cst0 = 0.0f, cst1 = 0.0f;
    for (int t = 0; t < S_LEN; t++) {
        float xv0 = 0.0f, xv1 = 0.0f;
        if (s8 == 0) {                                  // prefetch, independent of h
            xv0 = __ldg(d_xw + (size_t)t * ZW + row0);
            xv1 = __ldg(d_xw + (size_t)t * ZW + row1);
        }
        float acc0 = 0.0f, acc1 = 0.0f;
        if (t > 0) {
            if (u == 0) wait_flag_lane((volatile int*)&d_flg_w[lane * 32], t);
            __syncthreads();
            if (tid < HW / 4) {
                float4 v = __ldcg((const float4*)(out + (size_t)(t - 1) * HW) + tid);
                ((float4*)hs)[tid] = v;
            }
            __syncthreads();
            #pragma unroll
            for (int kk = 0; kk < 16; kk++) {
                float4 hv = *(const float4*)(hs + s8 * 4 + kk * 32);
                acc0 += w0[kk*4+0]*hv.x + w0[kk*4+1]*hv.y + w0[kk*4+2]*hv.z + w0[kk*4+3]*hv.w;
                acc1 += w1[kk*4+0]*hv.x + w1[kk*4+1]*hv.y + w1[kk*4+2]*hv.z + w1[kk*4+3]*hv.w;
            }
        }
        #pragma unroll
        for (int d = 4; d >= 1; d >>= 1) {
            acc0 += __shfl_xor_sync(0xffffffffu, acc0, d);
            acc1 += __shfl_xor_sync(0xffffffffu, acc1, d);
        }
        acc0 += xv0;  acc1 += xv1;                      // valid on lanes 0,8,16,24
        float zf0 = __shfl_sync(0xffffffffu, acc0, 8);
        float zg0 = __shfl_sync(0xffffffffu, acc0, 16);
        float zo0 = __shfl_sync(0xffffffffu, acc0, 24);
        float zf1 = __shfl_sync(0xffffffffu, acc1, 8);
        float zg1 = __shfl_sync(0xffffffffu, acc1, 16);
        float zo1 = __shfl_sync(0xffffffffu, acc1, 24);
        if (lane == 0) {
            cst0 = sigm(zf0) * cst0 + sigm(acc0) * tanhf(zg0);
            float h0 = sigm(zo0) * tanhf(cst0);
            cst1 = sigm(zf1) * cst1 + sigm(acc1) * tanhf(zg1);
            float h1 = sigm(zo1) * tanhf(cst1);
            __stcg(out + (size_t)t * HW + j0, h0);
            __stcg(out + (size_t)t * HW + j1, h1);
        }
        __syncthreads();
        if (tid == 0) {
            __threadfence();                            // single-thread publication fence
            *(volatile int*)&d_flg_w[blockIdx.x * 32] = t + 1;
        }
    }
}

// ---------------- launch ----------------
extern "C" void kernel_launch(void* const* d_in, const int* in_sizes, int n_in,
                              void* d_out, int out_size) {
    const float* E_char  = (const float*)d_in[0];
    const float* W_ih_r  = (const float*)d_in[1];
    const float* W_hh_r  = (const float*)d_in[2];
    const float* b_r     = (const float*)d_in[3];
    const float* W_lat   = (const float*)d_in[4];
    const float* b_lat   = (const float*)d_in[5];
    const float* E_word  = (const float*)d_in[6];
    const float* W_ih_w  = (const float*)d_in[7];
    const float* W_hh_w  = (const float*)d_in[8];
    const float* b_w     = (const float*)d_in[9];
    const int*   word_ids = (const int*)d_in[10];
    const int*   char_ids = (const int*)d_in[11];
    float* out = (float*)d_out;

    k_fill<<<1, 1024>>>();                     // zero word flags each run
    k_zalpha<<<A_SZ, 256>>>(E_char, W_ih_r, b_r);
    k_char<<<CL, 256>>>(W_hh_r, char_ids);     // one 8-CTA cluster
    k_wordin<<<S_LEN / 16, 256>>>(W_lat, b_lat, E_word, W_ih_w, b_w, word_ids);
    k_word<<<GBLK, 256>>>(W_hh_w, out);
}

// round 9
// speedup vs baseline: 2.9236x; 1.4922x over previous
#include <cuda_runtime.h>
#include <cuda_bf16.h>
#include <cstdint>

// Problem constants
#define S_LEN   4096
#define K_CH    4
#define NCHAR   (S_LEN * K_CH)      // 16384 char steps
#define A_SZ    25
#define EC      64
#define HR      256
#define DL      128
#define EW      128
#define HW      512
#define ZR      (4 * HR)            // 1024
#define ZW      (4 * HW)            // 2048
#define GBLK    32                  // CTAs for the word recurrence
#define CL      8                   // cluster size for the char recurrence

// ---------------- scratch (static __device__ — no allocations) ----------------
__device__ float d_zalpha[A_SZ * ZR];          // per-letter char input projection (+b_r)
__device__ float d_hword[S_LEN * HR];          // char-LSTM h at word boundaries only
__device__ float d_xw[S_LEN * ZW];             // word-LSTM input projections (+b_w)
__device__ int   d_flg_w[GBLK * 32];           // word per-CTA monotonic step flags

#define SENT 0xFFFFFFFFu                        // negative NaN; h in (-1,1) never encodes it

// ---------------- helpers ----------------
__device__ __forceinline__ float sigm(float x) { return 1.0f / (1.0f + __expf(-x)); }

__device__ __forceinline__ uint32_t smem_u32(const void* p) {
    uint32_t a;
    asm("{ .reg .u64 t; cvta.to.shared.u64 t, %1; cvt.u32.u64 %0, t; }" : "=r"(a) : "l"(p));
    return a;
}
__device__ __forceinline__ uint32_t mapa_rank(uint32_t laddr, uint32_t rank) {
    uint32_t r;
    asm("mapa.shared::cluster.u32 %0, %1, %2;" : "=r"(r) : "r"(laddr), "r"(rank));
    return r;
}
__device__ __forceinline__ void st_cluster_v4(uint32_t raddr, float a, float b, float c, float d) {
    asm volatile("st.shared::cluster.v4.f32 [%0], {%1,%2,%3,%4};"
                 :: "r"(raddr), "f"(a), "f"(b), "f"(c), "f"(d) : "memory");
}
__device__ __forceinline__ uint32_t my_cluster_rank() {
    uint32_t r; asm("mov.u32 %0, %%cluster_ctarank;" : "=r"(r)); return r;
}
__device__ __forceinline__ void wait_flag_lane(volatile int* f, int t) {
    int guard = 0;
    while (*f < t) { if (++guard > (1 << 16)) break; }
}

// ---------------- K-1: zero the word flag array ----------------
__global__ void k_fill() {
    int i = threadIdx.x;
    if (i < GBLK * 32) d_flg_w[i] = 0;
}

// ---------------- K0: Z_alpha = E_char @ W_ih_r^T + b_r  [25 x 1024] ----------------
__global__ void k_zalpha(const float* __restrict__ E_char,
                         const float* __restrict__ W_ih_r,
                         const float* __restrict__ b_r) {
    __shared__ float es[EC];
    int a = blockIdx.x;
    if (threadIdx.x < EC) es[threadIdx.x] = E_char[a * EC + threadIdx.x];
    __syncthreads();
    for (int r = threadIdx.x; r < ZR; r += blockDim.x) {
        float acc = b_r[r];
        const float* wr = W_ih_r + r * EC;
        #pragma unroll 16
        for (int e = 0; e < EC; e++) acc += wr[e] * es[e];
        d_zalpha[a * ZR + r] = acc;
    }
}

// ---------------- K1: char-LSTM — 8-CTA cluster, lane = (unit, gate, slice) ----------
// CTA rank owns units [32r,32r+32); warp u owns units jb..jb+3 (jb=32r+4u).
// lane = m*8 + q*2 + s2 : unit m, gate q, dot-slice s2. One shfl_xor reduces the dot;
// activations are one-per-lane (parallel); cell update redundant across the unit's lanes.
// Exchange: DSMEM push + local sentinel poll (protocol identical to the passing R8 kernel).
__global__ void __launch_bounds__(256, 1) __cluster_dims__(CL, 1, 1)
k_char(const float* __restrict__ W_hh, const int* __restrict__ cid) {
    __shared__ float hbuf[2][HR];                 // double-buffered h exchange slots
    const int tid  = threadIdx.x;
    const int u    = tid >> 5;
    const int lane = tid & 31;
    const int m    = lane >> 3;                   // unit within warp (0..3)
    const int q    = (lane >> 1) & 3;             // gate (i,f,g,o)
    const int s2   = lane & 1;                    // dot slice (0..1)
    const uint32_t rank = my_cluster_rank();
    const int jb   = (int)rank * 32 + u * 4;
    const int j    = jb + m;
    const int row  = q * HR + j;

    // per-lane weights: W_row[s2*4 + kk*8 + e], 128 floats
    float w[128];
    #pragma unroll
    for (int kk = 0; kk < 32; kk++) {
        float4 v = *(const float4*)(W_hh + (size_t)row * HR + s2 * 4 + kk * 8);
        w[kk*4+0] = v.x; w[kk*4+1] = v.y; w[kk*4+2] = v.z; w[kk*4+3] = v.w;
    }

    // sentinel both slots; cluster-sync before anyone publishes
    ((uint32_t*)hbuf)[tid]      = SENT;
    ((uint32_t*)hbuf)[tid + HR] = SENT;
    __syncthreads();
    asm volatile("barrier.cluster.arrive.aligned;" ::: "memory");
    asm volatile("barrier.cluster.wait.aligned;"   ::: "memory");

    const uint32_t hb_base = smem_u32(hbuf);
    float cst = 0.0f;

    for (int t = 0; t < NCHAR; t++) {
        float xv = __ldg(d_zalpha + __ldg(cid + t) * ZR + row);   // independent; issues early
        float z;
        if (t > 0) {
            const int ps = (t - 1) & 1;
            {   // each thread polls one word of the previous-step slot (local SMEM)
                volatile uint32_t* p = (volatile uint32_t*)&hbuf[ps][0] + tid;
                int g = 0;
                while (*p == SENT) { if (++g > (1 << 16)) break; }
            }
            __syncthreads();
            float a0 = 0.f, a1 = 0.f, a2 = 0.f, a3 = 0.f;
            #pragma unroll
            for (int kk = 0; kk < 32; kk++) {
                float4 hv = *(const float4*)(&hbuf[ps][s2 * 4 + kk * 8]);
                a0 += w[kk*4+0] * hv.x;  a1 += w[kk*4+1] * hv.y;
                a2 += w[kk*4+2] * hv.z;  a3 += w[kk*4+3] * hv.w;
            }
            __syncthreads();                               // all reads of slot ps done
            ((uint32_t*)&hbuf[ps][0])[tid] = SENT;         // re-sentinel for epoch t+1
            __syncthreads();                               // re-sentinel before publish
            float zp = (a0 + a1) + (a2 + a3);
            zp += __shfl_xor_sync(0xffffffffu, zp, 1);     // combine the 2 slices
            z = zp + xv;
        } else {
            z = xv;
        }
        // one activation per lane, in parallel (gate g -> tanh, others -> sigmoid)
        float act = (q == 2) ? tanhf(z) : sigm(z);
        const int base = lane & 24;                        // m*8
        float ai = __shfl_sync(0xffffffffu, act, base + 0);
        float af = __shfl_sync(0xffffffffu, act, base + 2);
        float ag = __shfl_sync(0xffffffffu, act, base + 4);
        float ao = __shfl_sync(0xffffffffu, act, base + 6);
        cst = af * cst + ai * ag;                          // redundant per-unit, consistent
        float h = ao * tanhf(cst);
        // gather the warp's 4 unit outputs
        float h0 = __shfl_sync(0xffffffffu, h, 0);
        float h1 = __shfl_sync(0xffffffffu, h, 8);
        float h2 = __shfl_sync(0xffffffffu, h, 16);
        float h3 = __shfl_sync(0xffffffffu, h, 24);
        // push into all 8 CTAs' hbuf[t&1] (incl. self)
        if (lane < CL) {
            uint32_t laddr = hb_base + (uint32_t)(((t & 1) * HR + jb) * 4);
            st_cluster_v4(mapa_rank(laddr, (uint32_t)lane), h0, h1, h2, h3);
        }
        // word-boundary h to global for the word-LSTM input stage
        if ((t & 3) == 3 && lane == 0)
            *(float4*)&d_hword[(size_t)(t >> 2) * HR + jb] = make_float4(h0, h1, h2, h3);
    }
    asm volatile("barrier.cluster.arrive.aligned;" ::: "memory");
    asm volatile("barrier.cluster.wait.aligned;"   ::: "memory");
}

// ---------------- K2: latent + word input projections ----------------
__global__ void __launch_bounds__(256)
k_wordin(const float* __restrict__ W_lat, const float* __restrict__ b_lat,
         const float* __restrict__ E_word, const float* __restrict__ W_ih_w,
         const float* __restrict__ b_w,   const int* __restrict__ word_ids) {
    __shared__ float hw[16 * HR];          // 16 KB
    __shared__ float us[16 * (EW + DL)];   // 16 KB : [si][0:128)=we, [128:256)=latent
    const int tid = threadIdx.x;
    const int s0  = blockIdx.x * 16;

    #pragma unroll
    for (int i = 0; i < 16; i++)
        hw[i * HR + tid] = d_hword[(size_t)(s0 + i) * HR + tid];
    for (int idx = tid; idx < 16 * EW; idx += 256) {
        int si = idx >> 7, e = idx & 127;
        us[si * 256 + e] = __ldg(E_word + (size_t)__ldg(word_ids + s0 + si) * EW + e);
    }
    __syncthreads();

    for (int idx = tid; idx < 16 * DL; idx += 256) {
        int si = idx >> 7, d = idx & 127;
        float acc = b_lat[d];
        const float* wr = W_lat + d * HR;
        #pragma unroll 8
        for (int l = 0; l < HR; l++) acc += __ldg(wr + l) * hw[si * HR + l];
        us[si * 256 + 128 + d] = tanhf(acc);
    }
    __syncthreads();

    for (int rr = 0; rr < 8; rr++) {
        int r = tid + rr * 256;
        const float* wr = W_ih_w + (size_t)r * 256;
        float bb = b_w[r];
        float acc[16];
        #pragma unroll
        for (int si = 0; si < 16; si++) acc[si] = bb;
        for (int c = 0; c < 256; c++) {
            float wv = __ldg(wr + c);
            #pragma unroll
            for (int si = 0; si < 16; si++) acc[si] += wv * us[si * 256 + c];
        }
        #pragma unroll
        for (int si = 0; si < 16; si++) d_xw[(size_t)(s0 + si) * ZW + r] = acc[si];
    }
}

// ---------------- K3: word-LSTM — 32 CTAs x 256 thr, lane = (unit, gate, slice) ------
// lane = m*16 + q*4 + s4 : unit m (2/warp), gate q, dot-slice s4 (4). Two shfl_xor
// reduce the dot; activations one-per-lane. L2 flag exchange (R6-proven).
__global__ void __launch_bounds__(256, 1)
k_word(const float* __restrict__ W_hh, float* __restrict__ out) {
    __shared__ float hs[HW];
    const int tid  = threadIdx.x;
    const int u    = tid >> 5;
    const int lane = tid & 31;
    const int m    = lane >> 4;                   // unit within warp (0..1)
    const int q    = (lane >> 2) & 3;             // gate
    const int s4   = lane & 3;                    // dot slice (0..3)
    const int j    = blockIdx.x * 16 + u * 2 + m;
    const int row  = q * HW + j;

    // per-lane weights: W_row[s4*4 + kk*16 + e], 128 floats
    float w[128];
    #pragma unroll
    for (int kk = 0; kk < 32; kk++) {
        float4 v = *(const float4*)(W_hh + (size_t)row * HW + s4 * 4 + kk * 16);
        w[kk*4+0] = v.x; w[kk*4+1] = v.y; w[kk*4+2] = v.z; w[kk*4+3] = v.w;
    }

    float cst = 0.0f;
    for (int t = 0; t < S_LEN; t++) {
        float xv = __ldg(d_xw + (size_t)t * ZW + row);    // independent; issues early
        float z;
        if (t > 0) {
            if (u == 0) wait_flag_lane((volatile int*)&d_flg_w[lane * 32], t);
            __syncthreads();
            if (tid < HW / 4) {
                float4 v = __ldcg((const float4*)(out + (size_t)(t - 1) * HW) + tid);
                ((float4*)hs)[tid] = v;
            }
            __syncthreads();
            float a0 = 0.f, a1 = 0.f, a2 = 0.f, a3 = 0.f;
            #pragma unroll
            for (int kk = 0; kk < 32; kk++) {
                float4 hv = *(const float4*)(&hs[s4 * 4 + kk * 16]);
                a0 += w[kk*4+0] * hv.x;  a1 += w[kk*4+1] * hv.y;
                a2 += w[kk*4+2] * hv.z;  a3 += w[kk*4+3] * hv.w;
            }
            float zp = (a0 + a1) + (a2 + a3);
            zp += __shfl_xor_sync(0xffffffffu, zp, 1);
            zp += __shfl_xor_sync(0xffffffffu, zp, 2);     // combine 4 slices
            z = zp + xv;
        } else {
            z = xv;
        }
        float act = (q == 2) ? tanhf(z) : sigm(z);
        const int base = lane & 16;                        // m*16
        float ai = __shfl_sync(0xffffffffu, act, base + 0);
        float af = __shfl_sync(0xffffffffu, act, base + 4);
        float ag = __shfl_sync(0xffffffffu, act, base + 8);
        float ao = __shfl_sync(0xffffffffu, act, base + 12);
        cst = af * cst + ai * ag;                          // redundant per-unit, consistent
        float h = ao * tanhf(cst);
        if ((lane & 15) == 0)                               // lanes 0 and 16 store their unit
            __stcg(out + (size_t)t * HW + j, h);
        __syncthreads();
        if (tid == 0) {
            __threadfence();                                // single-thread publication fence
            *(volatile int*)&d_flg_w[blockIdx.x * 32] = t + 1;
        }
    }
}

// ---------------- launch ----------------
extern "C" void kernel_launch(void* const* d_in, const int* in_sizes, int n_in,
                              void* d_out, int out_size) {
    const float* E_char  = (const float*)d_in[0];
    const float* W_ih_r  = (const float*)d_in[1];
    const float* W_hh_r  = (const float*)d_in[2];
    const float* b_r     = (const float*)d_in[3];
    const float* W_lat   = (const float*)d_in[4];
    const float* b_lat   = (const float*)d_in[5];
    const float* E_word  = (const float*)d_in[6];
    const float* W_ih_w  = (const float*)d_in[7];
    const float* W_hh_w  = (const float*)d_in[8];
    const float* b_w     = (const float*)d_in[9];
    const int*   word_ids = (const int*)d_in[10];
    const int*   char_ids = (const int*)d_in[11];
    float* out = (float*)d_out;

    k_fill<<<1, 1024>>>();                     // zero word flags each run
    k_zalpha<<<A_SZ, 256>>>(E_char, W_ih_r, b_r);
    k_char<<<CL, 256>>>(W_hh_r, char_ids);     // one 8-CTA cluster
    k_wordin<<<S_LEN / 16, 256>>>(W_lat, b_lat, E_word, W_ih_w, b_w, word_ids);
    k_word<<<GBLK, 256>>>(W_hh_w, out);
}

// round 14
// speedup vs baseline: 3.0022x; 1.0269x over previous
#include <cuda_runtime.h>
#include <cuda_bf16.h>
#include <cstdint>

// Problem constants
#define S_LEN   4096
#define K_CH    4
#define NCHAR   (S_LEN * K_CH)      // 16384 char steps
#define A_SZ    25
#define EC      64
#define HR      256
#define DL      128
#define EW      128
#define HW      512
#define ZR      (4 * HR)            // 1024
#define ZW      (4 * HW)            // 2048
#define WBLK    64                  // CTAs for the word recurrence (8 units each)
#define CL      8                   // cluster size for the char recurrence

#define SENT 0xFFFFFFFFu            // negative NaN; h in (-1,1) never encodes it

// ---------------- scratch (static __device__ — no allocations) ----------------
__device__ float d_zalpha[A_SZ * ZR];          // per-letter char input projection (+b_r)
__device__ float d_hword[S_LEN * HR];          // char-LSTM h at word boundaries only
__device__ float d_xw[S_LEN * ZW];             // word-LSTM input projections (+b_w)
__device__ int   d_flg_w[WBLK * 32];           // word per-CTA monotonic step flags

// ---------------- helpers ----------------
__device__ __forceinline__ float sigm(float x) { return 1.0f / (1.0f + __expf(-x)); }

__device__ __forceinline__ uint32_t smem_u32(const void* p) {
    uint32_t a;
    asm("{ .reg .u64 t; cvta.to.shared.u64 t, %1; cvt.u32.u64 %0, t; }" : "=r"(a) : "l"(p));
    return a;
}
__device__ __forceinline__ uint32_t mapa_rank(uint32_t laddr, uint32_t rank) {
    uint32_t r;
    asm("mapa.shared::cluster.u32 %0, %1, %2;" : "=r"(r) : "r"(laddr), "r"(rank));
    return r;
}
__device__ __forceinline__ void st_cluster_v4(uint32_t raddr, float a, float b, float c, float d) {
    asm volatile("st.shared::cluster.v4.f32 [%0], {%1,%2,%3,%4};"
                 :: "r"(raddr), "f"(a), "f"(b), "f"(c), "f"(d) : "memory");
}
__device__ __forceinline__ uint32_t my_cluster_rank() {
    uint32_t r; asm("mov.u32 %0, %%cluster_ctarank;" : "=r"(r)); return r;
}
// Word-LSTM flag spin (R6/R9-proven primitive).
__device__ __forceinline__ void wait_flag_lane(volatile int* f, int t) {
    int guard = 0;
    while (*f < t) { if (++guard > (1 << 16)) break; }
}
// ---- packed fp32x2 math (Blackwell FFMA2; halves FFMA instruction count) ----
__device__ __forceinline__ unsigned long long pk2(float lo, float hi) {
    unsigned long long r;
    asm("mov.b64 %0, {%1,%2};" : "=l"(r) : "f"(lo), "f"(hi));
    return r;
}
__device__ __forceinline__ void fma2(unsigned long long& d,
                                     unsigned long long a, unsigned long long b) {
    asm("fma.rn.f32x2 %0, %1, %2, %0;" : "+l"(d) : "l"(a), "l"(b));
}
__device__ __forceinline__ float upk_sum(unsigned long long v) {
    float lo, hi;
    asm("mov.b64 {%0,%1}, %2;" : "=f"(lo), "=f"(hi) : "l"(v));
    return lo + hi;
}

// ---------------- K-1: zero the word flag array ----------------
__global__ void k_fill() {
    for (int i = threadIdx.x; i < WBLK * 32; i += blockDim.x) d_flg_w[i] = 0;
}

// ---------------- K0: Z_alpha = E_char @ W_ih_r^T + b_r  [25 x 1024] ----------------
__global__ void k_zalpha(const float* __restrict__ E_char,
                         const float* __restrict__ W_ih_r,
                         const float* __restrict__ b_r) {
    __shared__ float es[EC];
    int a = blockIdx.x;
    if (threadIdx.x < EC) es[threadIdx.x] = E_char[a * EC + threadIdx.x];
    __syncthreads();
    for (int r = threadIdx.x; r < ZR; r += blockDim.x) {
        float acc = b_r[r];
        const float* wr = W_ih_r + r * EC;
        #pragma unroll 16
        for (int e = 0; e < EC; e++) acc += wr[e] * es[e];
        d_zalpha[a * ZR + r] = acc;
    }
}

// ---------------- K1: char-LSTM — 8-CTA cluster, R9-PROVEN sentinel transport --------
// CTA rank owns units [32r,32r+32); warp u owns units jb..jb+3 (jb=32r+4u).
// lane = m*8 + q*2 + s2. Transport: sentinel double-buffer + re-sentinel, 3 bars/step
// (exact R9 protocol). Dot uses packed fma.rn.f32x2 (bit-identical pairing to R9).
__global__ void __launch_bounds__(256, 1) __cluster_dims__(CL, 1, 1)
k_char(const float* __restrict__ W_hh, const int* __restrict__ cid) {
    __shared__ __align__(16) float hbuf[2][HR];   // sentinel-initialized h exchange slots
    const int tid  = threadIdx.x;
    const int u    = tid >> 5;
    const int lane = tid & 31;
    const int m    = lane >> 3;                   // unit within warp (0..3)
    const int q    = (lane >> 1) & 3;             // gate (i,f,g,o)
    const int s2   = lane & 1;                    // dot slice (0..1)
    const uint32_t rank = my_cluster_rank();
    const int jb   = (int)rank * 32 + u * 4;
    const int j    = jb + m;
    const int row  = q * HR + j;

    // packed per-lane weights: pairs of W_row[s2*4 + kk*8 + e]
    unsigned long long w2[64];
    #pragma unroll
    for (int kk = 0; kk < 32; kk++) {
        float4 v = *(const float4*)(W_hh + (size_t)row * HR + s2 * 4 + kk * 8);
        w2[kk*2+0] = pk2(v.x, v.y);
        w2[kk*2+1] = pk2(v.z, v.w);
    }

    // sentinel both slots; cluster-sync so no CTA publishes before all are initialized
    ((uint32_t*)hbuf)[tid]      = SENT;
    ((uint32_t*)hbuf)[tid + HR] = SENT;
    __syncthreads();
    asm volatile("barrier.cluster.arrive.aligned;" ::: "memory");
    asm volatile("barrier.cluster.wait.aligned;"   ::: "memory");

    const uint32_t hb_base = smem_u32(hbuf);
    float cst = 0.0f;

    for (int t = 0; t < NCHAR; t++) {
        float xv = __ldg(d_zalpha + __ldg(cid + t) * ZR + row);   // issues early
        float acc = 0.0f;
        if (t > 0) {
            const int ps = (t - 1) & 1;
            {   // each thread polls one word of the previous-step slot (local SMEM)
                volatile uint32_t* p = (volatile uint32_t*)&hbuf[ps][0] + tid;
                int g = 0;
                while (*p == SENT) { if (++g > (1 << 16)) break; }
            }
            __syncthreads();
            unsigned long long a01 = 0ull, a23 = 0ull;
            #pragma unroll
            for (int kk = 0; kk < 32; kk++) {
                ulonglong2 hv = *(const ulonglong2*)(&hbuf[ps][s2 * 4 + kk * 8]);
                fma2(a01, w2[kk*2+0], hv.x);
                fma2(a23, w2[kk*2+1], hv.y);
            }
            acc = upk_sum(a01) + upk_sum(a23);     // == (a0+a1)+(a2+a3), bit-identical to R9
            __syncthreads();                        // all reads of slot ps done
            ((uint32_t*)&hbuf[ps][0])[tid] = SENT;  // re-sentinel for epoch t+1
            __syncthreads();                        // re-sentinel before publish
        }
        if (s2 == 0) acc += xv;                     // xv summed once per (unit,gate)
        acc += __shfl_xor_sync(0xffffffffu, acc, 1); // both slices -> full z on both lanes
        float act = (q == 2) ? tanhf(acc) : sigm(acc);
        const int base = lane & 24;                  // m*8
        float ai = __shfl_sync(0xffffffffu, act, base + 0);
        float af = __shfl_sync(0xffffffffu, act, base + 2);
        float ag = __shfl_sync(0xffffffffu, act, base + 4);
        float ao = __shfl_sync(0xffffffffu, act, base + 6);
        cst = af * cst + ai * ag;
        float h = ao * tanhf(cst);
        float h0 = __shfl_sync(0xffffffffu, h, 0);
        float h1 = __shfl_sync(0xffffffffu, h, 8);
        float h2 = __shfl_sync(0xffffffffu, h, 16);
        float h3 = __shfl_sync(0xffffffffu, h, 24);
        // push this warp's 4 h values into all 8 CTAs' hbuf[t&1] (incl. self) — R9-proven
        if (lane < CL) {
            uint32_t laddr = hb_base + (uint32_t)(((t & 1) * HR + jb) * 4);
            st_cluster_v4(mapa_rank(laddr, (uint32_t)lane), h0, h1, h2, h3);
        }
        if ((t & 3) == 3 && lane == 0)
            *(float4*)&d_hword[(size_t)(t >> 2) * HR + jb] = make_float4(h0, h1, h2, h3);
    }
    asm volatile("barrier.cluster.arrive.aligned;" ::: "memory");
    asm volatile("barrier.cluster.wait.aligned;"   ::: "memory");
}

// ---------------- K2: latent + word input projections ----------------
__global__ void __launch_bounds__(256)
k_wordin(const float* __restrict__ W_lat, const float* __restrict__ b_lat,
         const float* __restrict__ E_word, const float* __restrict__ W_ih_w,
         const float* __restrict__ b_w,   const int* __restrict__ word_ids) {
    __shared__ float hw[16 * HR];          // 16 KB
    __shared__ float us[16 * (EW + DL)];   // 16 KB : [si][0:128)=we, [128:256)=latent
    const int tid = threadIdx.x;
    const int s0  = blockIdx.x * 16;

    #pragma unroll
    for (int i = 0; i < 16; i++)
        hw[i * HR + tid] = d_hword[(size_t)(s0 + i) * HR + tid];
    for (int idx = tid; idx < 16 * EW; idx += 256) {
        int si = idx >> 7, e = idx & 127;
        us[si * 256 + e] = __ldg(E_word + (size_t)__ldg(word_ids + s0 + si) * EW + e);
    }
    __syncthreads();

    for (int idx = tid; idx < 16 * DL; idx += 256) {
        int si = idx >> 7, d = idx & 127;
        float acc = b_lat[d];
        const float* wr = W_lat + d * HR;
        #pragma unroll 8
        for (int l = 0; l < HR; l++) acc += __ldg(wr + l) * hw[si * HR + l];
        us[si * 256 + 128 + d] = tanhf(acc);
    }
    __syncthreads();

    for (int rr = 0; rr < 8; rr++) {
        int r = tid + rr * 256;
        const float* wr = W_ih_w + (size_t)r * 256;
        float bb = b_w[r];
        float acc[16];
        #pragma unroll
        for (int si = 0; si < 16; si++) acc[si] = bb;
        for (int c = 0; c < 256; c++) {
            float wv = __ldg(wr + c);
            #pragma unroll
            for (int si = 0; si < 16; si++) acc[si] += wv * us[si * 256 + c];
        }
        #pragma unroll
        for (int si = 0; si < 16; si++) d_xw[(size_t)(s0 + si) * ZW + r] = acc[si];
    }
}

// ---------------- K3: word-LSTM — 64 CTAs x 256 thr, R9-PROVEN flag transport --------
// CTA b owns units [8b,8b+8); warp u -> unit j=8b+u; lane = q*8 + s8.
// Transport: h via __stcg to out, tid0 fence + monotonic flag; consumers poll 64 flags
// (warps 0-1), then __ldcg the h row. Dot uses packed fma.rn.f32x2.
__global__ void __launch_bounds__(256, 1)
k_word(const float* __restrict__ W_hh, float* __restrict__ out) {
    __shared__ __align__(16) float hs[HW];
    const int tid  = threadIdx.x;
    const int u    = tid >> 5;
    const int lane = tid & 31;
    const int q    = lane >> 3;                   // gate
    const int s8   = lane & 7;                    // dot slice (0..7)
    const int j    = blockIdx.x * 8 + u;
    const int row  = q * HW + j;

    // packed per-lane weights: pairs of W_row[s8*4 + kk*32 + e]
    unsigned long long w2[32];
    #pragma unroll
    for (int kk = 0; kk < 16; kk++) {
        float4 v = *(const float4*)(W_hh + (size_t)row * HW + s8 * 4 + kk * 32);
        w2[kk*2+0] = pk2(v.x, v.y);
        w2[kk*2+1] = pk2(v.z, v.w);
    }

    float cst = 0.0f;
    for (int t = 0; t < S_LEN; t++) {
        float xv = 0.0f;
        if (s8 == 0) xv = __ldg(d_xw + (size_t)t * ZW + row);   // issues early
        float acc = 0.0f;
        if (t > 0) {
            if (u < 2) wait_flag_lane((volatile int*)&d_flg_w[(u * 32 + lane) * 32], t);
            __syncthreads();
            if (tid < HW / 4) {
                float4 v = __ldcg((const float4*)(out + (size_t)(t - 1) * HW) + tid);
                ((float4*)hs)[tid] = v;
            }
            __syncthreads();
            unsigned long long a01 = 0ull, a23 = 0ull;
            #pragma unroll
            for (int kk = 0; kk < 16; kk++) {
                ulonglong2 hv = *(const ulonglong2*)(&hs[s8 * 4 + kk * 32]);
                fma2(a01, w2[kk*2+0], hv.x);
                fma2(a23, w2[kk*2+1], hv.y);
            }
            acc = upk_sum(a01) + upk_sum(a23);
        }
        if (s8 == 0) acc += xv;
        acc += __shfl_xor_sync(0xffffffffu, acc, 4);
        acc += __shfl_xor_sync(0xffffffffu, acc, 2);
        acc += __shfl_xor_sync(0xffffffffu, acc, 1);   // all 8 lanes of gate hold z
        float act = (q == 2) ? tanhf(acc) : sigm(acc);
        float ai = __shfl_sync(0xffffffffu, act, 0);
        float af = __shfl_sync(0xffffffffu, act, 8);
        float ag = __shfl_sync(0xffffffffu, act, 16);
        float ao = __shfl_sync(0xffffffffu, act, 24);
        cst = af * cst + ai * ag;
        float h = ao * tanhf(cst);
        if (lane == 0) __stcg(out + (size_t)t * HW + j, h);
        __syncthreads();                               // h stores done; also guards hs reuse
        if (tid == 0) {
            __threadfence();                           // single-thread publication fence
            *(volatile int*)&d_flg_w[blockIdx.x * 32] = t + 1;
        }
    }
}

// ---------------- launch ----------------
extern "C" void kernel_launch(void* const* d_in, const int* in_sizes, int n_in,
                              void* d_out, int out_size) {
    const float* E_char  = (const float*)d_in[0];
    const float* W_ih_r  = (const float*)d_in[1];
    const float* W_hh_r  = (const float*)d_in[2];
    const float* b_r     = (const float*)d_in[3];
    const float* W_lat   = (const float*)d_in[4];
    const float* b_lat   = (const float*)d_in[5];
    const float* E_word  = (const float*)d_in[6];
    const float* W_ih_w  = (const float*)d_in[7];
    const float* W_hh_w  = (const float*)d_in[8];
    const float* b_w     = (const float*)d_in[9];
    const int*   word_ids = (const int*)d_in[10];
    const int*   char_ids = (const int*)d_in[11];
    float* out = (float*)d_out;

    k_fill<<<1, 1024>>>();                     // zero word flags each run
    k_zalpha<<<A_SZ, 256>>>(E_char, W_ih_r, b_r);
    k_char<<<CL, 256>>>(W_hh_r, char_ids);     // one 8-CTA cluster
    k_wordin<<<S_LEN / 16, 256>>>(W_lat, b_lat, E_word, W_ih_w, b_w, word_ids);
    k_word<<<WBLK, 256>>>(W_hh_w, out);
}

// round 15
// speedup vs baseline: 3.0788x; 1.0255x over previous
#include <cuda_runtime.h>
#include <cuda_bf16.h>
#include <cstdint>

// Problem constants
#define S_LEN   4096
#define K_CH    4
#define NCHAR   (S_LEN * K_CH)      // 16384 char steps
#define A_SZ    25
#define EC      64
#define HR      256
#define DL      128
#define EW      128
#define HW      512
#define ZR      (4 * HR)            // 1024
#define ZW      (4 * HW)            // 2048
#define WBLK    64                  // CTAs for the word recurrence (8 units each)
#define CL      8                   // cluster size for the char recurrence

#define SENT 0xFFFFFFFFu            // negative NaN; h in (-1,1) never encodes it

// ---------------- scratch (static __device__ — no allocations) ----------------
__device__ float d_zalpha[A_SZ * ZR];          // per-letter char input projection (+b_r)
__device__ float d_hword[S_LEN * HR];          // char-LSTM h at word boundaries only
__device__ float d_xw[S_LEN * ZW];             // word-LSTM input projections (+b_w)
__device__ int   d_flg_w[WBLK * 32];           // word per-CTA monotonic step flags

// ---------------- helpers ----------------
// fast sigmoid / tanh: MUFU-based, rel err ~1e-6 (output tolerance is 1e-3)
__device__ __forceinline__ float sigm(float x) {
    return __fdividef(1.0f, 1.0f + __expf(-x));
}
__device__ __forceinline__ float tanh_fast(float x) {
    float e = __expf(2.0f * x);
    return __fdividef(e - 1.0f, e + 1.0f);
}

__device__ __forceinline__ uint32_t smem_u32(const void* p) {
    uint32_t a;
    asm("{ .reg .u64 t; cvta.to.shared.u64 t, %1; cvt.u32.u64 %0, t; }" : "=r"(a) : "l"(p));
    return a;
}
__device__ __forceinline__ uint32_t mapa_rank(uint32_t laddr, uint32_t rank) {
    uint32_t r;
    asm("mapa.shared::cluster.u32 %0, %1, %2;" : "=r"(r) : "r"(laddr), "r"(rank));
    return r;
}
__device__ __forceinline__ void st_cluster_v4(uint32_t raddr, float a, float b, float c, float d) {
    asm volatile("st.shared::cluster.v4.f32 [%0], {%1,%2,%3,%4};"
                 :: "r"(raddr), "f"(a), "f"(b), "f"(c), "f"(d) : "memory");
}
__device__ __forceinline__ uint32_t my_cluster_rank() {
    uint32_t r; asm("mov.u32 %0, %%cluster_ctarank;" : "=r"(r)); return r;
}
// Word-LSTM flag spin (R6/R9/R14-proven primitive).
__device__ __forceinline__ void wait_flag_lane(volatile int* f, int t) {
    int guard = 0;
    while (*f < t) { if (++guard > (1 << 16)) break; }
}
// ---- packed fp32x2 math (Blackwell FFMA2) ----
__device__ __forceinline__ unsigned long long pk2(float lo, float hi) {
    unsigned long long r;
    asm("mov.b64 %0, {%1,%2};" : "=l"(r) : "f"(lo), "f"(hi));
    return r;
}
__device__ __forceinline__ void fma2(unsigned long long& d,
                                     unsigned long long a, unsigned long long b) {
    asm("fma.rn.f32x2 %0, %1, %2, %0;" : "+l"(d) : "l"(a), "l"(b));
}
__device__ __forceinline__ float upk_sum(unsigned long long v) {
    float lo, hi;
    asm("mov.b64 {%0,%1}, %2;" : "=f"(lo), "=f"(hi) : "l"(v));
    return lo + hi;
}

// ---------------- K-1: zero the word flag array ----------------
__global__ void k_fill() {
    for (int i = threadIdx.x; i < WBLK * 32; i += blockDim.x) d_flg_w[i] = 0;
}

// ---------------- K0: Z_alpha = E_char @ W_ih_r^T + b_r  [25 x 1024] ----------------
__global__ void k_zalpha(const float* __restrict__ E_char,
                         const float* __restrict__ W_ih_r,
                         const float* __restrict__ b_r) {
    __shared__ float es[EC];
    int a = blockIdx.x;
    if (threadIdx.x < EC) es[threadIdx.x] = E_char[a * EC + threadIdx.x];
    __syncthreads();
    for (int r = threadIdx.x; r < ZR; r += blockDim.x) {
        float acc = b_r[r];
        const float* wr = W_ih_r + r * EC;
        #pragma unroll 16
        for (int e = 0; e < EC; e++) acc += wr[e] * es[e];
        d_zalpha[a * ZR + r] = acc;
    }
}

// ---------------- K1: char-LSTM — 8-CTA cluster, 4-slot sentinel, 1 bar/step ---------
// CTA rank owns units [32r,32r+32); warp u owns units jb..jb+3 (jb=32r+4u).
// lane = m*8 + q*2 + s2. Transport = R9/R14 sentinel primitive, but 4 rotating slots:
//   step t: poll own word of slot (t-1)&3 -> ONE bar -> re-sentinel own word of slot
//   (t-2)&3 -> dot on slot (t-1)&3 -> compute -> push into slot t&3.
// Safety: each thread polls/re-sentinels ITS OWN word (same-thread ordering); the bar
// proves all local dots on the re-sentineled slot finished (they precede the polls);
// remote writes to that slot (epoch t+2's pushes) are causally >=2 epochs later.
__global__ void __launch_bounds__(256, 1) __cluster_dims__(CL, 1, 1)
k_char(const float* __restrict__ W_hh, const int* __restrict__ cid) {
    __shared__ __align__(16) float hbuf[4][HR];   // 4 rotating sentinel slots (4 KB)
    const int tid  = threadIdx.x;
    const int u    = tid >> 5;
    const int lane = tid & 31;
    const int m    = lane >> 3;                   // unit within warp (0..3)
    const int q    = (lane >> 1) & 3;             // gate (i,f,g,o)
    const int s2   = lane & 1;                    // dot slice (0..1)
    const uint32_t rank = my_cluster_rank();
    const int jb   = (int)rank * 32 + u * 4;
    const int j    = jb + m;
    const int row  = q * HR + j;

    // packed per-lane weights: pairs of W_row[s2*4 + kk*8 + e]
    unsigned long long w2[64];
    #pragma unroll
    for (int kk = 0; kk < 32; kk++) {
        float4 v = *(const float4*)(W_hh + (size_t)row * HR + s2 * 4 + kk * 8);
        w2[kk*2+0] = pk2(v.x, v.y);
        w2[kk*2+1] = pk2(v.z, v.w);
    }

    // sentinel all 4 slots; cluster-sync so no CTA publishes before all are initialized
    #pragma unroll
    for (int s = 0; s < 4; s++) ((uint32_t*)hbuf)[s * HR + tid] = SENT;
    __syncthreads();
    asm volatile("barrier.cluster.arrive.aligned;" ::: "memory");
    asm volatile("barrier.cluster.wait.aligned;"   ::: "memory");

    const uint32_t hb_base = smem_u32(hbuf);
    float cst = 0.0f;

    for (int t = 0; t < NCHAR; t++) {
        float xv = __ldg(d_zalpha + __ldg(cid + t) * ZR + row);   // issues early
        float acc = 0.0f;
        if (t > 0) {
            const int ps = (t - 1) & 3;
            {   // poll own word of the previous-step slot (local SMEM, volatile)
                volatile uint32_t* p = (volatile uint32_t*)&hbuf[ps][0] + tid;
                int g = 0;
                while (*p == SENT) { if (++g > (1 << 16)) break; }
            }
            __syncthreads();                        // the ONLY bar per step
            if (t >= 2)                             // deferred re-sentinel (own word)
                ((uint32_t*)&hbuf[(t - 2) & 3][0])[tid] = SENT;
            unsigned long long a01 = 0ull, a23 = 0ull;
            #pragma unroll
            for (int kk = 0; kk < 32; kk++) {
                ulonglong2 hv = *(const ulonglong2*)(&hbuf[ps][s2 * 4 + kk * 8]);
                fma2(a01, w2[kk*2+0], hv.x);
                fma2(a23, w2[kk*2+1], hv.y);
            }
            acc = upk_sum(a01) + upk_sum(a23);
        }
        if (s2 == 0) acc += xv;                     // xv summed once per (unit,gate)
        acc += __shfl_xor_sync(0xffffffffu, acc, 1); // both slices -> full z on both lanes
        float act = (q == 2) ? tanh_fast(acc) : sigm(acc);
        const int base = lane & 24;                  // m*8
        float ai = __shfl_sync(0xffffffffu, act, base + 0);
        float af = __shfl_sync(0xffffffffu, act, base + 2);
        float ag = __shfl_sync(0xffffffffu, act, base + 4);
        float ao = __shfl_sync(0xffffffffu, act, base + 6);
        cst = af * cst + ai * ag;
        float h = ao * tanh_fast(cst);
        float h0 = __shfl_sync(0xffffffffu, h, 0);
        float h1 = __shfl_sync(0xffffffffu, h, 8);
        float h2 = __shfl_sync(0xffffffffu, h, 16);
        float h3 = __shfl_sync(0xffffffffu, h, 24);
        // push this warp's 4 h values into all 8 CTAs' hbuf[t&3] (incl. self)
        if (lane < CL) {
            uint32_t laddr = hb_base + (uint32_t)(((t & 3) * HR + jb) * 4);
            st_cluster_v4(mapa_rank(laddr, (uint32_t)lane), h0, h1, h2, h3);
        }
        if ((t & 3) == 3 && lane == 0)
            *(float4*)&d_hword[(size_t)(t >> 2) * HR + jb] = make_float4(h0, h1, h2, h3);
    }
    asm volatile("barrier.cluster.arrive.aligned;" ::: "memory");
    asm volatile("barrier.cluster.wait.aligned;"   ::: "memory");
}

// ---------------- K2: latent + word input projections ----------------
__global__ void __launch_bounds__(256)
k_wordin(const float* __restrict__ W_lat, const float* __restrict__ b_lat,
         const float* __restrict__ E_word, const float* __restrict__ W_ih_w,
         const float* __restrict__ b_w,   const int* __restrict__ word_ids) {
    __shared__ float hw[16 * HR];          // 16 KB
    __shared__ float us[16 * (EW + DL)];   // 16 KB : [si][0:128)=we, [128:256)=latent
    const int tid = threadIdx.x;
    const int s0  = blockIdx.x * 16;

    #pragma unroll
    for (int i = 0; i < 16; i++)
        hw[i * HR + tid] = d_hword[(size_t)(s0 + i) * HR + tid];
    for (int idx = tid; idx < 16 * EW; idx += 256) {
        int si = idx >> 7, e = idx & 127;
        us[si * 256 + e] = __ldg(E_word + (size_t)__ldg(word_ids + s0 + si) * EW + e);
    }
    __syncthreads();

    for (int idx = tid; idx < 16 * DL; idx += 256) {
        int si = idx >> 7, d = idx & 127;
        float acc = b_lat[d];
        const float* wr = W_lat + d * HR;
        #pragma unroll 8
        for (int l = 0; l < HR; l++) acc += __ldg(wr + l) * hw[si * HR + l];
        us[si * 256 + 128 + d] = tanhf(acc);        // keep accurate tanh off critical path
    }
    __syncthreads();

    for (int rr = 0; rr < 8; rr++) {
        int r = tid + rr * 256;
        const float* wr = W_ih_w + (size_t)r * 256;
        float bb = b_w[r];
        float acc[16];
        #pragma unroll
        for (int si = 0; si < 16; si++) acc[si] = bb;
        for (int c = 0; c < 256; c++) {
            float wv = __ldg(wr + c);
            #pragma unroll
            for (int si = 0; si < 16; si++) acc[si] += wv * us[si * 256 + c];
        }
        #pragma unroll
        for (int si = 0; si < 16; si++) d_xw[(size_t)(s0 + si) * ZW + r] = acc[si];
    }
}

// ---------------- K3: word-LSTM — 64 CTAs x 256 thr, R14-PROVEN flag transport -------
// CTA b owns units [8b,8b+8); warp u -> unit j=8b+u; lane = q*8 + s8.
__global__ void __launch_bounds__(256, 1)
k_word(const float* __restrict__ W_hh, float* __restrict__ out) {
    __shared__ __align__(16) float hs[HW];
    const int tid  = threadIdx.x;
    const int u    = tid >> 5;
    const int lane = tid & 31;
    const int q    = lane >> 3;                   // gate
    const int s8   = lane & 7;                    // dot slice (0..7)
    const int j    = blockIdx.x * 8 + u;
    const int row  = q * HW + j;

    // packed per-lane weights: pairs of W_row[s8*4 + kk*32 + e]
    unsigned long long w2[32];
    #pragma unroll
    for (int kk = 0; kk < 16; kk++) {
        float4 v = *(const float4*)(W_hh + (size_t)row * HW + s8 * 4 + kk * 32);
        w2[kk*2+0] = pk2(v.x, v.y);
        w2[kk*2+1] = pk2(v.z, v.w);
    }

    float cst = 0.0f;
    for (int t = 0; t < S_LEN; t++) {
        float xv = 0.0f;
        if (s8 == 0) xv = __ldg(d_xw + (size_t)t * ZW + row);   // issues early
        float acc = 0.0f;
        if (t > 0) {
            if (u < 2) wait_flag_lane((volatile int*)&d_flg_w[(u * 32 + lane) * 32], t);
            __syncthreads();
            if (tid < HW / 4) {
                float4 v = __ldcg((const float4*)(out + (size_t)(t - 1) * HW) + tid);
                ((float4*)hs)[tid] = v;
            }
            __syncthreads();
            unsigned long long a01 = 0ull, a23 = 0ull;
            #pragma unroll
            for (int kk = 0; kk < 16; kk++) {
                ulonglong2 hv = *(const ulonglong2*)(&hs[s8 * 4 + kk * 32]);
                fma2(a01, w2[kk*2+0], hv.x);
                fma2(a23, w2[kk*2+1], hv.y);
            }
            acc = upk_sum(a01) + upk_sum(a23);
        }
        if (s8 == 0) acc += xv;
        acc += __shfl_xor_sync(0xffffffffu, acc, 4);
        acc += __shfl_xor_sync(0xffffffffu, acc, 2);
        acc += __shfl_xor_sync(0xffffffffu, acc, 1);   // all 8 lanes of gate hold z
        float act = (q == 2) ? tanh_fast(acc) : sigm(acc);
        float ai = __shfl_sync(0xffffffffu, act, 0);
        float af = __shfl_sync(0xffffffffu, act, 8);
        float ag = __shfl_sync(0xffffffffu, act, 16);
        float ao = __shfl_sync(0xffffffffu, act, 24);
        cst = af * cst + ai * ag;
        float h = ao * tanh_fast(cst);
        if (lane == 0) __stcg(out + (size_t)t * HW + j, h);
        __syncthreads();                               // h stores done; also guards hs reuse
        if (tid == 0) {
            __threadfence();                           // single-thread publication fence
            *(volatile int*)&d_flg_w[blockIdx.x * 32] = t + 1;
        }
    }
}

// ---------------- launch ----------------
extern "C" void kernel_launch(void* const* d_in, const int* in_sizes, int n_in,
                              void* d_out, int out_size) {
    const float* E_char  = (const float*)d_in[0];
    const float* W_ih_r  = (const float*)d_in[1];
    const float* W_hh_r  = (const float*)d_in[2];
    const float* b_r     = (const float*)d_in[3];
    const float* W_lat   = (const float*)d_in[4];
    const float* b_lat   = (const float*)d_in[5];
    const float* E_word  = (const float*)d_in[6];
    const float* W_ih_w  = (const float*)d_in[7];
    const float* W_hh_w  = (const float*)d_in[8];
    const float* b_w     = (const float*)d_in[9];
    const int*   word_ids = (const int*)d_in[10];
    const int*   char_ids = (const int*)d_in[11];
    float* out = (float*)d_out;

    k_fill<<<1, 1024>>>();                     // zero word flags each run
    k_zalpha<<<A_SZ, 256>>>(E_char, W_ih_r, b_r);
    k_char<<<CL, 256>>>(W_hh_r, char_ids);     // one 8-CTA cluster
    k_wordin<<<S_LEN / 16, 256>>>(W_lat, b_lat, E_word, W_ih_w, b_w, word_ids);
    k_word<<<WBLK, 256>>>(W_hh_w, out);
}

// round 16
// speedup vs baseline: 3.4649x; 1.1254x over previous
#include <cuda_runtime.h>
#include <cuda_bf16.h>
#include <cstdint>

// Problem constants
#define S_LEN   4096
#define K_CH    4
#define NCHAR   (S_LEN * K_CH)      // 16384 char steps
#define A_SZ    25
#define EC      64
#define HR      256
#define DL      128
#define EW      128
#define HW      512
#define ZR      (4 * HR)            // 1024
#define ZW      (4 * HW)            // 2048
#define WBLK    64                  // CTAs for the word recurrence (8 units each)
#define CL      8                   // cluster size for the char recurrence

#define SENT 0xFFFFFFFFu            // negative NaN; finite h never encodes it

// ---------------- scratch (static __device__ — no allocations) ----------------
__device__ float d_zalpha[A_SZ * ZR];          // per-letter char input projection (+b_r)
__device__ float d_hword[S_LEN * HR];          // char-LSTM h at word boundaries only
__device__ float d_xw[S_LEN * ZW];             // word-LSTM input projections (+b_w)
__device__ int   d_flg_w[WBLK * 32];           // word per-CTA monotonic step flags

// ---------------- helpers ----------------
// single-MUFU activations (tanh.approx, sm_75+): ~16 cyc vs ~45 for exp+div
__device__ __forceinline__ float tanh_a(float x) {
    float r; asm("tanh.approx.f32 %0, %1;" : "=f"(r) : "f"(x)); return r;
}
__device__ __forceinline__ float sigm(float x) {
    return fmaf(tanh_a(0.5f * x), 0.5f, 0.5f);
}

__device__ __forceinline__ uint32_t smem_u32(const void* p) {
    uint32_t a;
    asm("{ .reg .u64 t; cvta.to.shared.u64 t, %1; cvt.u32.u64 %0, t; }" : "=r"(a) : "l"(p));
    return a;
}
__device__ __forceinline__ uint32_t mapa_rank(uint32_t laddr, uint32_t rank) {
    uint32_t r;
    asm("mapa.shared::cluster.u32 %0, %1, %2;" : "=r"(r) : "r"(laddr), "r"(rank));
    return r;
}
__device__ __forceinline__ void st_cluster_f32(uint32_t raddr, float v) {
    asm volatile("st.shared::cluster.f32 [%0], %1;" :: "r"(raddr), "f"(v) : "memory");
}
__device__ __forceinline__ uint32_t my_cluster_rank() {
    uint32_t r; asm("mov.u32 %0, %%cluster_ctarank;" : "=r"(r)); return r;
}
// Word-LSTM flag spin (R6/R9/R14/R15-proven primitive).
__device__ __forceinline__ void wait_flag_lane(volatile int* f, int t) {
    int guard = 0;
    while (*f < t) { if (++guard > (1 << 16)) break; }
}
// ---- packed fp32x2 math (Blackwell FFMA2) ----
__device__ __forceinline__ unsigned long long pk2(float lo, float hi) {
    unsigned long long r;
    asm("mov.b64 %0, {%1,%2};" : "=l"(r) : "f"(lo), "f"(hi));
    return r;
}
__device__ __forceinline__ void fma2(unsigned long long& d,
                                     unsigned long long a, unsigned long long b) {
    asm("fma.rn.f32x2 %0, %1, %2, %0;" : "+l"(d) : "l"(a), "l"(b));
}
__device__ __forceinline__ float upk_sum(unsigned long long v) {
    float lo, hi;
    asm("mov.b64 {%0,%1}, %2;" : "=f"(lo), "=f"(hi) : "l"(v));
    return lo + hi;
}

// ---------------- K-1: zero the word flag array ----------------
__global__ void k_fill() {
    for (int i = threadIdx.x; i < WBLK * 32; i += blockDim.x) d_flg_w[i] = 0;
}

// ---------------- K0: Z_alpha = E_char @ W_ih_r^T + b_r  [25 x 1024] ----------------
__global__ void k_zalpha(const float* __restrict__ E_char,
                         const float* __restrict__ W_ih_r,
                         const float* __restrict__ b_r) {
    __shared__ float es[EC];
    int a = blockIdx.x;
    if (threadIdx.x < EC) es[threadIdx.x] = E_char[a * EC + threadIdx.x];
    __syncthreads();
    for (int r = threadIdx.x; r < ZR; r += blockDim.x) {
        float acc = b_r[r];
        const float* wr = W_ih_r + r * EC;
        #pragma unroll 16
        for (int e = 0; e < EC; e++) acc += wr[e] * es[e];
        d_zalpha[a * ZR + r] = acc;
    }
}

// ---------------- K1: char-LSTM — 8-CTA cluster, 4-slot sentinel, 1 bar/step ---------
// CTA rank owns units [32r,32r+32); warp u owns units jb..jb+3 (jb=32r+4u).
// lane = m*8 + q*2 + s2. Transport = R9/R15-proven value-is-sentinel DSMEM push with
// 4 rotating slots + deferred re-sentinel (1 bar/step). NEW: no gather shfls — every
// lane pushes ITS unit's h (all 8 lanes of a unit hold h) as one scalar cluster store
// to rank lane&7 (32 stores = 4 units x 8 ranks, same destination set as before).
__global__ void __launch_bounds__(256, 1) __cluster_dims__(CL, 1, 1)
k_char(const float* __restrict__ W_hh, const int* __restrict__ cid) {
    __shared__ __align__(16) float hbuf[4][HR];   // 4 rotating sentinel slots (4 KB)
    const int tid  = threadIdx.x;
    const int u    = tid >> 5;
    const int lane = tid & 31;
    const int m    = lane >> 3;                   // unit within warp (0..3)
    const int q    = (lane >> 1) & 3;             // gate (i,f,g,o)
    const int s2   = lane & 1;                    // dot slice (0..1)
    const uint32_t rank = my_cluster_rank();
    const int jb   = (int)rank * 32 + u * 4;
    const int j    = jb + m;
    const int row  = q * HR + j;

    // packed per-lane weights: pairs of W_row[s2*4 + kk*8 + e]
    unsigned long long w2[64];
    #pragma unroll
    for (int kk = 0; kk < 32; kk++) {
        float4 v = *(const float4*)(W_hh + (size_t)row * HR + s2 * 4 + kk * 8);
        w2[kk*2+0] = pk2(v.x, v.y);
        w2[kk*2+1] = pk2(v.z, v.w);
    }

    // sentinel all 4 slots; cluster-sync so no CTA publishes before all are initialized
    #pragma unroll
    for (int s = 0; s < 4; s++) ((uint32_t*)hbuf)[s * HR + tid] = SENT;
    __syncthreads();
    asm volatile("barrier.cluster.arrive.aligned;" ::: "memory");
    asm volatile("barrier.cluster.wait.aligned;"   ::: "memory");

    const uint32_t hb_base = smem_u32(hbuf);
    float cst = 0.0f;

    for (int t = 0; t < NCHAR; t++) {
        float xv = __ldg(d_zalpha + __ldg(cid + t) * ZR + row);   // issues early
        float acc = 0.0f;
        if (t > 0) {
            const int ps = (t - 1) & 3;
            {   // poll own word of the previous-step slot (local SMEM, volatile)
                volatile uint32_t* p = (volatile uint32_t*)&hbuf[ps][0] + tid;
                int g = 0;
                while (*p == SENT) { if (++g > (1 << 16)) break; }
            }
            __syncthreads();                        // the ONLY bar per step
            if (t >= 2)                             // deferred re-sentinel (own word)
                ((uint32_t*)&hbuf[(t - 2) & 3][0])[tid] = SENT;
            unsigned long long a01 = 0ull, a23 = 0ull;
            #pragma unroll
            for (int kk = 0; kk < 32; kk++) {
                ulonglong2 hv = *(const ulonglong2*)(&hbuf[ps][s2 * 4 + kk * 8]);
                fma2(a01, w2[kk*2+0], hv.x);
                fma2(a23, w2[kk*2+1], hv.y);
            }
            acc = upk_sum(a01) + upk_sum(a23);
        }
        if (s2 == 0) acc += xv;                     // xv summed once per (unit,gate)
        acc += __shfl_xor_sync(0xffffffffu, acc, 1); // both slices -> full z on both lanes
        float act = (q == 2) ? tanh_a(acc) : sigm(acc);
        const int base = lane & 24;                  // m*8
        float ai = __shfl_sync(0xffffffffu, act, base + 0);
        float af = __shfl_sync(0xffffffffu, act, base + 2);
        float ag = __shfl_sync(0xffffffffu, act, base + 4);
        float ao = __shfl_sync(0xffffffffu, act, base + 6);
        cst = af * cst + ai * ag;                    // redundant per-unit, consistent
        float h = ao * tanh_a(cst);                  // every lane holds its unit's h
        // per-lane direct push: lane (m,q,s2) -> rank lane&7, unit j, slot t&3
        {
            uint32_t laddr = hb_base + (uint32_t)(((t & 3) * HR + j) * 4);
            st_cluster_f32(mapa_rank(laddr, (uint32_t)(lane & 7)), h);
        }
        // word-boundary h to global (one lane per unit; off critical path)
        if ((t & 3) == 3 && (lane & 7) == 0)
            d_hword[(size_t)(t >> 2) * HR + j] = h;
    }
    asm volatile("barrier.cluster.arrive.aligned;" ::: "memory");
    asm volatile("barrier.cluster.wait.aligned;"   ::: "memory");
}

// ---------------- K2: latent + word input projections ----------------
__global__ void __launch_bounds__(256)
k_wordin(const float* __restrict__ W_lat, const float* __restrict__ b_lat,
         const float* __restrict__ E_word, const float* __restrict__ W_ih_w,
         const float* __restrict__ b_w,   const int* __restrict__ word_ids) {
    __shared__ float hw[16 * HR];          // 16 KB
    __shared__ float us[16 * (EW + DL)];   // 16 KB : [si][0:128)=we, [128:256)=latent
    const int tid = threadIdx.x;
    const int s0  = blockIdx.x * 16;

    #pragma unroll
    for (int i = 0; i < 16; i++)
        hw[i * HR + tid] = d_hword[(size_t)(s0 + i) * HR + tid];
    for (int idx = tid; idx < 16 * EW; idx += 256) {
        int si = idx >> 7, e = idx & 127;
        us[si * 256 + e] = __ldg(E_word + (size_t)__ldg(word_ids + s0 + si) * EW + e);
    }
    __syncthreads();

    for (int idx = tid; idx < 16 * DL; idx += 256) {
        int si = idx >> 7, d = idx & 127;
        float acc = b_lat[d];
        const float* wr = W_lat + d * HR;
        #pragma unroll 8
        for (int l = 0; l < HR; l++) acc += __ldg(wr + l) * hw[si * HR + l];
        us[si * 256 + 128 + d] = tanhf(acc);        // accurate tanh off critical path
    }
    __syncthreads();

    for (int rr = 0; rr < 8; rr++) {
        int r = tid + rr * 256;
        const float* wr = W_ih_w + (size_t)r * 256;
        float bb = b_w[r];
        float acc[16];
        #pragma unroll
        for (int si = 0; si < 16; si++) acc[si] = bb;
        for (int c = 0; c < 256; c++) {
            float wv = __ldg(wr + c);
            #pragma unroll
            for (int si = 0; si < 16; si++) acc[si] += wv * us[si * 256 + c];
        }
        #pragma unroll
        for (int si = 0; si < 16; si++) d_xw[(size_t)(s0 + si) * ZW + r] = acc[si];
    }
}

// ---------------- K3: word-LSTM — 64 CTAs x 256 thr, merged poll+load, 2 bars --------
// CTA b owns units [8b,8b+8); warp u -> unit j=8b+u; lane = q*8 + s8.
// NEW: thread tid (<128) polls the flag of the CTA owning ITS float4 (tid>>1), then
// immediately __ldcg's it — per-thread chaining instead of poll-stage/bar/load-stage.
__global__ void __launch_bounds__(256, 1)
k_word(const float* __restrict__ W_hh, float* __restrict__ out) {
    __shared__ __align__(16) float hs[HW];
    const int tid  = threadIdx.x;
    const int u    = tid >> 5;
    const int lane = tid & 31;
    const int q    = lane >> 3;                   // gate
    const int s8   = lane & 7;                    // dot slice (0..7)
    const int j    = blockIdx.x * 8 + u;
    const int row  = q * HW + j;

    // packed per-lane weights: pairs of W_row[s8*4 + kk*32 + e]
    unsigned long long w2[32];
    #pragma unroll
    for (int kk = 0; kk < 16; kk++) {
        float4 v = *(const float4*)(W_hh + (size_t)row * HW + s8 * 4 + kk * 32);
        w2[kk*2+0] = pk2(v.x, v.y);
        w2[kk*2+1] = pk2(v.z, v.w);
    }

    float cst = 0.0f;
    for (int t = 0; t < S_LEN; t++) {
        float xv = 0.0f;
        if (s8 == 0) xv = __ldg(d_xw + (size_t)t * ZW + row);   // issues early
        float acc = 0.0f;
        if (t > 0) {
            if (tid < HW / 4) {
                // poll the producing CTA's flag, then load its float4 (units 4tid..4tid+3)
                wait_flag_lane((volatile int*)&d_flg_w[(tid >> 1) * 32], t);
                float4 v = __ldcg((const float4*)(out + (size_t)(t - 1) * HW) + tid);
                ((float4*)hs)[tid] = v;
            }
            __syncthreads();                       // bar 1: hs complete
            unsigned long long a01 = 0ull, a23 = 0ull;
            #pragma unroll
            for (int kk = 0; kk < 16; kk++) {
                ulonglong2 hv = *(const ulonglong2*)(&hs[s8 * 4 + kk * 32]);
                fma2(a01, w2[kk*2+0], hv.x);
                fma2(a23, w2[kk*2+1], hv.y);
            }
            acc = upk_sum(a01) + upk_sum(a23);
        }
        if (s8 == 0) acc += xv;
        acc += __shfl_xor_sync(0xffffffffu, acc, 4);
        acc += __shfl_xor_sync(0xffffffffu, acc, 2);
        acc += __shfl_xor_sync(0xffffffffu, acc, 1);   // all 8 lanes of gate hold z
        float act = (q == 2) ? tanh_a(acc) : sigm(acc);
        float ai = __shfl_sync(0xffffffffu, act, 0);
        float af = __shfl_sync(0xffffffffu, act, 8);
        float ag = __shfl_sync(0xffffffffu, act, 16);
        float ao = __shfl_sync(0xffffffffu, act, 24);
        cst = af * cst + ai * ag;
        float h = ao * tanh_a(cst);
        if (lane == 0) __stcg(out + (size_t)t * HW + j, h);
        __syncthreads();                               // bar 2: stores done + hs reads done
        if (tid == 0) {
            __threadfence();                           // single-thread publication fence
            *(volatile int*)&d_flg_w[blockIdx.x * 32] = t + 1;
        }
    }
}

// ---------------- launch ----------------
extern "C" void kernel_launch(void* const* d_in, const int* in_sizes, int n_in,
                              void* d_out, int out_size) {
    const float* E_char  = (const float*)d_in[0];
    const float* W_ih_r  = (const float*)d_in[1];
    const float* W_hh_r  = (const float*)d_in[2];
    const float* b_r     = (const float*)d_in[3];
    const float* W_lat   = (const float*)d_in[4];
    const float* b_lat   = (const float*)d_in[5];
    const float* E_word  = (const float*)d_in[6];
    const float* W_ih_w  = (const float*)d_in[7];
    const float* W_hh_w  = (const float*)d_in[8];
    const float* b_w     = (const float*)d_in[9];
    const int*   word_ids = (const int*)d_in[10];
    const int*   char_ids = (const int*)d_in[11];
    float* out = (float*)d_out;

    k_fill<<<1, 1024>>>();                     // zero word flags each run
    k_zalpha<<<A_SZ, 256>>>(E_char, W_ih_r, b_r);
    k_char<<<CL, 256>>>(W_hh_r, char_ids);     // one 8-CTA cluster
    k_wordin<<<S_LEN / 16, 256>>>(W_lat, b_lat, E_word, W_ih_w, b_w, word_ids);
    k_word<<<WBLK, 256>>>(W_hh_w, out);
}